// round 8
// baseline (speedup 1.0000x reference)
#include <cuda_runtime.h>
#include <cuda_bf16.h>
#include <cstdint>
#include <cstddef>

// Problem constants
#define BB 2
#define LL 2048
#define EE 2048
#define HQ 16
#define HKV 2
#define DD 128
#define MROWS (BB*LL)   // 4096

// ---------------------------------------------------------------------------
// Scratch (device globals — no allocations allowed)
// ---------------------------------------------------------------------------
__device__ float g_q[(size_t)MROWS * HQ * DD];     // 32 MB
__device__ float g_k[(size_t)MROWS * HKV * DD];    // 4 MB
__device__ float g_v[(size_t)MROWS * HKV * DD];    // 4 MB
__device__ float g_attn[(size_t)MROWS * HQ * DD];  // 32 MB

// bf16 split activations (reused for X and for attn output)
__device__ __nv_bfloat16 g_ah[(size_t)MROWS * EE];
__device__ __nv_bfloat16 g_al[(size_t)MROWS * EE];
// bf16 split transposed weights [N, K] (K-major)
__device__ __nv_bfloat16 g_wqh[(size_t)(HQ*DD) * EE];
__device__ __nv_bfloat16 g_wql[(size_t)(HQ*DD) * EE];
__device__ __nv_bfloat16 g_wkh[(size_t)(HKV*DD) * EE];
__device__ __nv_bfloat16 g_wkl[(size_t)(HKV*DD) * EE];
__device__ __nv_bfloat16 g_wvh[(size_t)(HKV*DD) * EE];
__device__ __nv_bfloat16 g_wvl[(size_t)(HKV*DD) * EE];
__device__ __nv_bfloat16 g_woh[(size_t)EE * (HQ*DD)];
__device__ __nv_bfloat16 g_wol[(size_t)EE * (HQ*DD)];

// ---------------------------------------------------------------------------
// PTX helpers (base-ISA only: cp.async / ldmatrix / mma.sync — no tcgen05)
// ---------------------------------------------------------------------------
__device__ __forceinline__ uint32_t smem_u32(const void* p) {
    uint32_t a;
    asm("{ .reg .u64 t; cvta.to.shared.u64 t, %1; cvt.u32.u64 %0, t; }"
        : "=r"(a) : "l"(p));
    return a;
}

__device__ __forceinline__ void cpa16(uint32_t d, const void* s) {
    asm volatile("cp.async.cg.shared.global [%0], [%1], 16;" :: "r"(d), "l"(s));
}
#define CP_COMMIT() asm volatile("cp.async.commit_group;")
#define CP_WAIT(n)  asm volatile("cp.async.wait_group %0;" :: "n"(n))

__device__ __forceinline__ void ldmx4(uint32_t a, uint32_t r[4]) {
    asm volatile("ldmatrix.sync.aligned.m8n8.x4.shared.b16 {%0,%1,%2,%3}, [%4];"
                 : "=r"(r[0]), "=r"(r[1]), "=r"(r[2]), "=r"(r[3]) : "r"(a));
}
__device__ __forceinline__ void ldmx2(uint32_t a, uint32_t r[2]) {
    asm volatile("ldmatrix.sync.aligned.m8n8.x2.shared.b16 {%0,%1}, [%2];"
                 : "=r"(r[0]), "=r"(r[1]) : "r"(a));
}

__device__ __forceinline__ void mma16816(float c[4], const uint32_t a[4],
                                         const uint32_t b[2]) {
    asm volatile(
        "mma.sync.aligned.m16n8k16.row.col.f32.bf16.bf16.f32 "
        "{%0,%1,%2,%3}, {%4,%5,%6,%7}, {%8,%9}, {%0,%1,%2,%3};"
        : "+f"(c[0]), "+f"(c[1]), "+f"(c[2]), "+f"(c[3])
        : "r"(a[0]), "r"(a[1]), "r"(a[2]), "r"(a[3]), "r"(b[0]), "r"(b[1]));
}

// ---------------------------------------------------------------------------
// split: fp32 -> bf16 hi + bf16 lo (elementwise, vectorized)
// ---------------------------------------------------------------------------
__global__ void split_kernel(const float* __restrict__ x,
                             __nv_bfloat16* __restrict__ h,
                             __nv_bfloat16* __restrict__ l, int n4)
{
    int i = blockIdx.x * blockDim.x + threadIdx.x;
    if (i >= n4) return;
    float4 v = ((const float4*)x)[i];
    __nv_bfloat16 h0 = __float2bfloat16(v.x);
    __nv_bfloat16 h1 = __float2bfloat16(v.y);
    __nv_bfloat16 h2 = __float2bfloat16(v.z);
    __nv_bfloat16 h3 = __float2bfloat16(v.w);
    __nv_bfloat16 l0 = __float2bfloat16(v.x - __bfloat162float(h0));
    __nv_bfloat16 l1 = __float2bfloat16(v.y - __bfloat162float(h1));
    __nv_bfloat16 l2 = __float2bfloat16(v.z - __bfloat162float(h2));
    __nv_bfloat16 l3 = __float2bfloat16(v.w - __bfloat162float(h3));
    ((__nv_bfloat162*)h)[2*i]   = __halves2bfloat162(h0, h1);
    ((__nv_bfloat162*)h)[2*i+1] = __halves2bfloat162(h2, h3);
    ((__nv_bfloat162*)l)[2*i]   = __halves2bfloat162(l0, l1);
    ((__nv_bfloat162*)l)[2*i+1] = __halves2bfloat162(l2, l3);
}

// ---------------------------------------------------------------------------
// transpose+split: W[K,N] fp32 -> Th,Tl [N,K] bf16
// ---------------------------------------------------------------------------
__global__ void tsplit_kernel(const float* __restrict__ W,
                              __nv_bfloat16* __restrict__ Th,
                              __nv_bfloat16* __restrict__ Tl, int K, int N)
{
    __shared__ float ts[32][33];
    const int n0 = blockIdx.x * 32, k0 = blockIdx.y * 32;
    const int tx = threadIdx.x, ty = threadIdx.y;   // 32 x 8
    for (int i = ty; i < 32; i += 8)
        ts[i][tx] = W[(size_t)(k0 + i) * N + n0 + tx];
    __syncthreads();
    for (int i = ty; i < 32; i += 8) {
        float v = ts[tx][i];  // = W[k0+tx][n0+i]
        __nv_bfloat16 hv = __float2bfloat16(v);
        __nv_bfloat16 lv = __float2bfloat16(v - __bfloat162float(hv));
        size_t o = (size_t)(n0 + i) * K + k0 + tx;
        Th[o] = hv;
        Tl[o] = lv;
    }
}

// ---------------------------------------------------------------------------
// bf16x3 GEMM via mma.sync: C[M,N] = A @ B^T (+bias)
//   A given as Ahi/Alo [M,K] bf16 row-major
//   B given as Bhi/Blo [N,K] bf16 row-major (W pre-transposed)
// CTA tile 128x128, BK=32, 8 warps (2 x 4), warp tile 64x32, double-buffered
// cp.async. Smem rows padded to 40 bf16 (80 B) for conflict-free ldmatrix.
// ---------------------------------------------------------------------------
#define BKG 32
#define SROW 80                     // bytes per padded smem row
#define TBYTES (128 * SROW)         // 10240 per matrix tile
#define BUFBYTES (4 * TBYTES)       // Ah, Al, Bh, Bl
#define GSMEM_BYTES (2 * BUFBYTES)  // 81920

__device__ __forceinline__ void tile_cp(uint32_t sdst,
                                        const __nv_bfloat16* __restrict__ g,
                                        int ldk, int row0, int k0, int t)
{
    const char* gb = (const char*)(g + (size_t)row0 * ldk + k0);
    const size_t rs = (size_t)ldk * 2;
#pragma unroll
    for (int i = 0; i < 2; i++) {
        int idx = t + i * 256;          // 0..511
        int r = idx >> 2;               // row 0..127
        int c = (idx & 3) << 4;         // byte 0,16,32,48
        cpa16(sdst + r * SROW + c, gb + (size_t)r * rs + c);
    }
}

__global__ __launch_bounds__(256)
void gemm_bf16x3(const __nv_bfloat16* __restrict__ Ah,
                 const __nv_bfloat16* __restrict__ Al,
                 const __nv_bfloat16* __restrict__ Bh,
                 const __nv_bfloat16* __restrict__ Bl,
                 const float* __restrict__ bias,
                 float* __restrict__ C, int M, int N, int K)
{
    extern __shared__ char sm[];
    const uint32_t sbase = smem_u32(sm);
    const int t = threadIdx.x;
    const int wid = t >> 5, lane = t & 31;
    const int wm = wid & 1, wn = wid >> 1;       // 2 x 4 warp grid
    const int bm = blockIdx.y * 128, bn = blockIdx.x * 128;
    const int NT = K / BKG;

    float acc[4][4][4];
#pragma unroll
    for (int mt = 0; mt < 4; mt++)
#pragma unroll
        for (int nt = 0; nt < 4; nt++)
#pragma unroll
            for (int i = 0; i < 4; i++) acc[mt][nt][i] = 0.f;

    // Prologue: chunk 0 -> buffer 0
    {
        uint32_t s0 = sbase;
        tile_cp(s0,              Ah, K, bm, 0, t);
        tile_cp(s0 + TBYTES,     Al, K, bm, 0, t);
        tile_cp(s0 + 2 * TBYTES, Bh, K, bn, 0, t);
        tile_cp(s0 + 3 * TBYTES, Bl, K, bn, 0, t);
        CP_COMMIT();
    }

    // ldmatrix per-thread source addresses (within a tile)
    const int q = lane >> 3, r8 = lane & 7;
    const int arow = wm * 64 + (q & 1) * 8 + r8;
    const int acolb = ((q >> 1) * 8) * 2;            // byte offset of k-quad
    const int t16 = lane & 15;
    const int brow = wn * 32 + (t16 & 7);
    const int bcolb = ((t16 >> 3) * 8) * 2;

    for (int kt = 0; kt < NT; kt++) {
        const uint32_t sb = sbase + (kt & 1) * BUFBYTES;
        if (kt + 1 < NT) {
            const uint32_t sn = sbase + ((kt + 1) & 1) * BUFBYTES;
            const int k0 = (kt + 1) * BKG;
            tile_cp(sn,              Ah, K, bm, k0, t);
            tile_cp(sn + TBYTES,     Al, K, bm, k0, t);
            tile_cp(sn + 2 * TBYTES, Bh, K, bn, k0, t);
            tile_cp(sn + 3 * TBYTES, Bl, K, bn, k0, t);
            CP_COMMIT();
            CP_WAIT(1);
        } else {
            CP_WAIT(0);
        }
        __syncthreads();

#pragma unroll
        for (int kk = 0; kk < 2; kk++) {
            const uint32_t abase = sb + arow * SROW + kk * 32 + acolb;
            const uint32_t bbase = sb + 2 * TBYTES + brow * SROW + kk * 32 + bcolb;
            uint32_t ah_[4][4], al_[4][4], bh_[4][2], bl_[4][2];
#pragma unroll
            for (int mt = 0; mt < 4; mt++) {
                ldmx4(abase + mt * 16 * SROW, ah_[mt]);
                ldmx4(abase + TBYTES + mt * 16 * SROW, al_[mt]);
            }
#pragma unroll
            for (int nt = 0; nt < 4; nt++) {
                ldmx2(bbase + nt * 8 * SROW, bh_[nt]);
                ldmx2(bbase + TBYTES + nt * 8 * SROW, bl_[nt]);
            }
#pragma unroll
            for (int mt = 0; mt < 4; mt++)
#pragma unroll
                for (int nt = 0; nt < 4; nt++) {
                    mma16816(acc[mt][nt], ah_[mt], bh_[nt]);
                    mma16816(acc[mt][nt], ah_[mt], bl_[nt]);
                    mma16816(acc[mt][nt], al_[mt], bh_[nt]);
                }
        }
        __syncthreads();
    }

    // Epilogue: C fragment layout m16n8 f32: c0/c1 row gid col 2tid(+1); c2/c3 row gid+8
    const int gid = lane >> 2, tid2 = (lane & 3) * 2;
#pragma unroll
    for (int mt = 0; mt < 4; mt++) {
        const int row = bm + wm * 64 + mt * 16 + gid;
#pragma unroll
        for (int nt = 0; nt < 4; nt++) {
            const int col = bn + wn * 32 + nt * 8 + tid2;
            float b0 = 0.f, b1 = 0.f;
            if (bias) { b0 = bias[col]; b1 = bias[col + 1]; }
            float2 v0 = make_float2(acc[mt][nt][0] + b0, acc[mt][nt][1] + b1);
            float2 v1 = make_float2(acc[mt][nt][2] + b0, acc[mt][nt][3] + b1);
            *(float2*)&C[(size_t)row * N + col] = v0;
            *(float2*)&C[(size_t)(row + 8) * N + col] = v1;
        }
    }
}

// ---------------------------------------------------------------------------
// RoPE in-place on x[B*L, H*D]
// ---------------------------------------------------------------------------
__global__ void rope_kernel(float* __restrict__ x, int H)
{
    __shared__ float cs[64], sn[64];
    const int row = blockIdx.x;
    const int pos = row & (LL - 1);
    const int t = threadIdx.x;
    if (t < 64) {
        float e   = (float)(2 * t) * (1.0f / (float)DD);
        float inv = powf(1000000.0f, -e);
        float ang = (float)pos * inv;
        cs[t] = cosf(ang);
        sn[t] = sinf(ang);
    }
    __syncthreads();
    float* xr = x + (size_t)row * H * DD;
    for (int i = t; i < H * 64; i += blockDim.x) {
        int h = i >> 6;
        int d = i & 63;
        float x1 = xr[h * DD + d];
        float x2 = xr[h * DD + d + 64];
        float c = cs[d], s = sn[d];
        xr[h * DD + d]      = x1 * c - x2 * s;
        xr[h * DD + d + 64] = x2 * c + x1 * s;
    }
}

// ---------------------------------------------------------------------------
// Flash attention, causal, GQA (G=8). One block = one (b,h) x 64-query tile.
// ---------------------------------------------------------------------------
#define ATTN_SMEM_FLOATS (64*128 + 64*132 + 64*128 + 64*65)

__global__ __launch_bounds__(256) void attn_kernel(
    const float* __restrict__ q, const float* __restrict__ k,
    const float* __restrict__ v, float* __restrict__ o_out)
{
    extern __shared__ float smf[];
    float* Qs = smf;                      // [64][128]
    float* Ks = Qs + 64 * 128;            // [64][132]
    float* Vs = Ks + 64 * 132;            // [64][128]
    float* Ps = Vs + 64 * 128;            // [64][65]

    const int t  = threadIdx.x;
    const int ty = t >> 4;
    const int tx = t & 15;
    const int qt = blockIdx.x;
    const int bh = blockIdx.y;
    const int b  = bh >> 4;
    const int h  = bh & 15;
    const int hk = h >> 3;
    const int q0 = qt * 64;

    {
        const float* qptr = q + ((size_t)(b * LL + q0)) * (HQ * DD) + h * DD;
        for (int i = t; i < 64 * 32; i += 256) {
            int r = i >> 5;
            int c = (i & 31) << 2;
            *(float4*)&Qs[r * 128 + c] = *(const float4*)&qptr[(size_t)r * (HQ * DD) + c];
        }
    }

    float m_[4], l_[4], o_[4][8];
#pragma unroll
    for (int r = 0; r < 4; r++) {
        m_[r] = -1e30f;
        l_[r] = 0.f;
#pragma unroll
        for (int c = 0; c < 8; c++) o_[r][c] = 0.f;
    }
    const float scale = 0.08838834764831845f;

    for (int kt = 0; kt <= qt; kt++) {
        __syncthreads();
        {
            const float* kptr = k + ((size_t)(b * LL + kt * 64)) * (HKV * DD) + hk * DD;
            const float* vptr = v + ((size_t)(b * LL + kt * 64)) * (HKV * DD) + hk * DD;
            for (int i = t; i < 64 * 32; i += 256) {
                int r = i >> 5;
                int c = (i & 31) << 2;
                *(float4*)&Ks[r * 132 + c] = *(const float4*)&kptr[(size_t)r * (HKV * DD) + c];
                *(float4*)&Vs[r * 128 + c] = *(const float4*)&vptr[(size_t)r * (HKV * DD) + c];
            }
        }
        __syncthreads();

        float s_[4][4];
#pragma unroll
        for (int r = 0; r < 4; r++)
#pragma unroll
            for (int c = 0; c < 4; c++) s_[r][c] = 0.f;

#pragma unroll 4
        for (int k4 = 0; k4 < 32; k4++) {
            float4 ra[4], rb[4];
#pragma unroll
            for (int r = 0; r < 4; r++)
                ra[r] = *(float4*)&Qs[(ty * 4 + r) * 128 + k4 * 4];
#pragma unroll
            for (int c = 0; c < 4; c++)
                rb[c] = *(float4*)&Ks[(tx + 16 * c) * 132 + k4 * 4];
#pragma unroll
            for (int r = 0; r < 4; r++)
#pragma unroll
                for (int c = 0; c < 4; c++)
                    s_[r][c] += ra[r].x * rb[c].x + ra[r].y * rb[c].y +
                                ra[r].z * rb[c].z + ra[r].w * rb[c].w;
        }

        const bool diag = (kt == qt);
#pragma unroll
        for (int r = 0; r < 4; r++) {
            const int qi = q0 + ty * 4 + r;
            float mx = -1e30f;
#pragma unroll
            for (int c = 0; c < 4; c++) {
                int ki = kt * 64 + tx + 16 * c;
                float val = s_[r][c] * scale;
                if (diag && ki > qi) val = -1e30f;
                s_[r][c] = val;
                mx = fmaxf(mx, val);
            }
#pragma unroll
            for (int off = 8; off >= 1; off >>= 1)
                mx = fmaxf(mx, __shfl_xor_sync(0xffffffffu, mx, off));
            float mnew = fmaxf(m_[r], mx);
            float corr = __expf(m_[r] - mnew);
            float sum = 0.f;
#pragma unroll
            for (int c = 0; c < 4; c++) {
                float p = __expf(s_[r][c] - mnew);
                sum += p;
                Ps[(ty * 4 + r) * 65 + tx + 16 * c] = p;
            }
#pragma unroll
            for (int off = 8; off >= 1; off >>= 1)
                sum += __shfl_xor_sync(0xffffffffu, sum, off);
            l_[r] = l_[r] * corr + sum;
            m_[r] = mnew;
#pragma unroll
            for (int c = 0; c < 8; c++) o_[r][c] *= corr;
        }
        __syncthreads();

#pragma unroll 4
        for (int kk = 0; kk < 64; kk++) {
            float pv[4];
#pragma unroll
            for (int r = 0; r < 4; r++)
                pv[r] = Ps[(ty * 4 + r) * 65 + kk];
#pragma unroll
            for (int c = 0; c < 8; c++) {
                float vv = Vs[kk * 128 + tx + 16 * c];
#pragma unroll
                for (int r = 0; r < 4; r++)
                    o_[r][c] += pv[r] * vv;
            }
        }
    }

#pragma unroll
    for (int r = 0; r < 4; r++) {
        float inv = 1.0f / l_[r];
        size_t rowoff = ((size_t)(b * LL + q0 + ty * 4 + r)) * (HQ * DD) + h * DD;
#pragma unroll
        for (int c = 0; c < 8; c++)
            o_out[rowoff + tx + 16 * c] = o_[r][c] * inv;
    }
}

// ---------------------------------------------------------------------------
// Launch
// ---------------------------------------------------------------------------
extern "C" void kernel_launch(void* const* d_in, const int* in_sizes, int n_in,
                              void* d_out, int out_size)
{
    const float* X  = (const float*)d_in[0];
    const float* Wq = (const float*)d_in[1];
    const float* bq = (const float*)d_in[2];
    const float* Wk = (const float*)d_in[3];
    const float* bk = (const float*)d_in[4];
    const float* Wv = (const float*)d_in[5];
    const float* bv = (const float*)d_in[6];
    const float* Wo = (const float*)d_in[7];
    float* out = (float*)d_out;

    float *qp, *kp, *vp, *ap;
    __nv_bfloat16 *ah, *al, *wqh, *wql, *wkh, *wkl, *wvh, *wvl, *woh, *wol;
    cudaGetSymbolAddress((void**)&qp, g_q);
    cudaGetSymbolAddress((void**)&kp, g_k);
    cudaGetSymbolAddress((void**)&vp, g_v);
    cudaGetSymbolAddress((void**)&ap, g_attn);
    cudaGetSymbolAddress((void**)&ah, g_ah);
    cudaGetSymbolAddress((void**)&al, g_al);
    cudaGetSymbolAddress((void**)&wqh, g_wqh);
    cudaGetSymbolAddress((void**)&wql, g_wql);
    cudaGetSymbolAddress((void**)&wkh, g_wkh);
    cudaGetSymbolAddress((void**)&wkl, g_wkl);
    cudaGetSymbolAddress((void**)&wvh, g_wvh);
    cudaGetSymbolAddress((void**)&wvl, g_wvl);
    cudaGetSymbolAddress((void**)&woh, g_woh);
    cudaGetSymbolAddress((void**)&wol, g_wol);

    cudaFuncSetAttribute(gemm_bf16x3,
                         cudaFuncAttributeMaxDynamicSharedMemorySize, GSMEM_BYTES);

    const int n4 = (int)((size_t)MROWS * EE / 4);

    // Split activations + transpose/split weights
    split_kernel<<<(n4 + 255) / 256, 256>>>(X, ah, al, n4);
    tsplit_kernel<<<dim3((HQ*DD)/32, EE/32), dim3(32, 8)>>>(Wq, wqh, wql, EE, HQ*DD);
    tsplit_kernel<<<dim3((HKV*DD)/32, EE/32), dim3(32, 8)>>>(Wk, wkh, wkl, EE, HKV*DD);
    tsplit_kernel<<<dim3((HKV*DD)/32, EE/32), dim3(32, 8)>>>(Wv, wvh, wvl, EE, HKV*DD);
    tsplit_kernel<<<dim3(EE/32, (HQ*DD)/32), dim3(32, 8)>>>(Wo, woh, wol, HQ*DD, EE);

    // QKV projections (mma.sync bf16x3)
    gemm_bf16x3<<<dim3((HQ*DD)/128, MROWS/128), 256, GSMEM_BYTES>>>(
        ah, al, wqh, wql, bq, qp, MROWS, HQ*DD, EE);
    gemm_bf16x3<<<dim3((HKV*DD)/128, MROWS/128), 256, GSMEM_BYTES>>>(
        ah, al, wkh, wkl, bk, kp, MROWS, HKV*DD, EE);
    gemm_bf16x3<<<dim3((HKV*DD)/128, MROWS/128), 256, GSMEM_BYTES>>>(
        ah, al, wvh, wvl, bv, vp, MROWS, HKV*DD, EE);

    // RoPE
    rope_kernel<<<MROWS, 256>>>(qp, HQ);
    rope_kernel<<<MROWS, 256>>>(kp, HKV);

    // Attention (fp32 SIMT flash)
    const int attn_smem = ATTN_SMEM_FLOATS * (int)sizeof(float);
    cudaFuncSetAttribute(attn_kernel, cudaFuncAttributeMaxDynamicSharedMemorySize, attn_smem);
    attn_kernel<<<dim3(LL / 64, BB * HQ), 256, attn_smem>>>(qp, kp, vp, ap);

    // Output projection: split attn output, then GEMM (no bias)
    split_kernel<<<(n4 + 255) / 256, 256>>>(ap, ah, al, n4);
    gemm_bf16x3<<<dim3(EE/128, MROWS/128), 256, GSMEM_BYTES>>>(
        ah, al, woh, wol, nullptr, out, MROWS, EE, EE);
}

// round 9
// speedup vs baseline: 1.6505x; 1.6505x over previous
#include <cuda_runtime.h>
#include <cuda_bf16.h>
#include <cstdint>
#include <cstddef>

// Problem constants
#define BB 2
#define LL 2048
#define EE 2048
#define HQ 16
#define HKV 2
#define DD 128
#define MROWS (BB*LL)   // 4096

// ---------------------------------------------------------------------------
// Scratch (device globals — no allocations allowed)
// ---------------------------------------------------------------------------
__device__ float g_q[(size_t)MROWS * HQ * DD];     // 32 MB
__device__ float g_k[(size_t)MROWS * HKV * DD];    // 4 MB
__device__ float g_v[(size_t)MROWS * HKV * DD];    // 4 MB
__device__ float g_attn[(size_t)MROWS * HQ * DD];  // 32 MB

// bf16 split activations (X -> gemms; then Q hi/lo; then attn-out)
__device__ __nv_bfloat16 g_ah[(size_t)MROWS * EE];
__device__ __nv_bfloat16 g_al[(size_t)MROWS * EE];
// bf16 split K / V (post-rope for K)
__device__ __nv_bfloat16 g_kh2[(size_t)MROWS * HKV * DD];
__device__ __nv_bfloat16 g_kl2[(size_t)MROWS * HKV * DD];
__device__ __nv_bfloat16 g_vh2[(size_t)MROWS * HKV * DD];
__device__ __nv_bfloat16 g_vl2[(size_t)MROWS * HKV * DD];
// bf16 split transposed weights [N, K] (K-major)
__device__ __nv_bfloat16 g_wqh[(size_t)(HQ*DD) * EE];
__device__ __nv_bfloat16 g_wql[(size_t)(HQ*DD) * EE];
__device__ __nv_bfloat16 g_wkh[(size_t)(HKV*DD) * EE];
__device__ __nv_bfloat16 g_wkl[(size_t)(HKV*DD) * EE];
__device__ __nv_bfloat16 g_wvh[(size_t)(HKV*DD) * EE];
__device__ __nv_bfloat16 g_wvl[(size_t)(HKV*DD) * EE];
__device__ __nv_bfloat16 g_woh[(size_t)EE * (HQ*DD)];
__device__ __nv_bfloat16 g_wol[(size_t)EE * (HQ*DD)];

// ---------------------------------------------------------------------------
// PTX helpers (base-ISA: cp.async / ldmatrix / mma.sync)
// ---------------------------------------------------------------------------
__device__ __forceinline__ uint32_t smem_u32(const void* p) {
    uint32_t a;
    asm("{ .reg .u64 t; cvta.to.shared.u64 t, %1; cvt.u32.u64 %0, t; }"
        : "=r"(a) : "l"(p));
    return a;
}

__device__ __forceinline__ void cpa16(uint32_t d, const void* s) {
    asm volatile("cp.async.cg.shared.global [%0], [%1], 16;" :: "r"(d), "l"(s));
}
#define CP_COMMIT() asm volatile("cp.async.commit_group;")
#define CP_WAIT(n)  asm volatile("cp.async.wait_group %0;" :: "n"(n))

__device__ __forceinline__ void ldmx4(uint32_t a, uint32_t r[4]) {
    asm volatile("ldmatrix.sync.aligned.m8n8.x4.shared.b16 {%0,%1,%2,%3}, [%4];"
                 : "=r"(r[0]), "=r"(r[1]), "=r"(r[2]), "=r"(r[3]) : "r"(a));
}
__device__ __forceinline__ void ldmx2(uint32_t a, uint32_t r[2]) {
    asm volatile("ldmatrix.sync.aligned.m8n8.x2.shared.b16 {%0,%1}, [%2];"
                 : "=r"(r[0]), "=r"(r[1]) : "r"(a));
}
__device__ __forceinline__ void ldmx4t(uint32_t a, uint32_t r[4]) {
    asm volatile("ldmatrix.sync.aligned.m8n8.x4.trans.shared.b16 {%0,%1,%2,%3}, [%4];"
                 : "=r"(r[0]), "=r"(r[1]), "=r"(r[2]), "=r"(r[3]) : "r"(a));
}

__device__ __forceinline__ void mma16816(float c[4], const uint32_t a[4],
                                         const uint32_t b[2]) {
    asm volatile(
        "mma.sync.aligned.m16n8k16.row.col.f32.bf16.bf16.f32 "
        "{%0,%1,%2,%3}, {%4,%5,%6,%7}, {%8,%9}, {%0,%1,%2,%3};"
        : "+f"(c[0]), "+f"(c[1]), "+f"(c[2]), "+f"(c[3])
        : "r"(a[0]), "r"(a[1]), "r"(a[2]), "r"(a[3]), "r"(b[0]), "r"(b[1]));
}

// ---------------------------------------------------------------------------
// split: fp32 -> bf16 hi + bf16 lo
// ---------------------------------------------------------------------------
__global__ void split_kernel(const float* __restrict__ x,
                             __nv_bfloat16* __restrict__ h,
                             __nv_bfloat16* __restrict__ l, int n4)
{
    int i = blockIdx.x * blockDim.x + threadIdx.x;
    if (i >= n4) return;
    float4 v = ((const float4*)x)[i];
    __nv_bfloat16 h0 = __float2bfloat16(v.x);
    __nv_bfloat16 h1 = __float2bfloat16(v.y);
    __nv_bfloat16 h2 = __float2bfloat16(v.z);
    __nv_bfloat16 h3 = __float2bfloat16(v.w);
    __nv_bfloat16 l0 = __float2bfloat16(v.x - __bfloat162float(h0));
    __nv_bfloat16 l1 = __float2bfloat16(v.y - __bfloat162float(h1));
    __nv_bfloat16 l2 = __float2bfloat16(v.z - __bfloat162float(h2));
    __nv_bfloat16 l3 = __float2bfloat16(v.w - __bfloat162float(h3));
    ((__nv_bfloat162*)h)[2*i]   = __halves2bfloat162(h0, h1);
    ((__nv_bfloat162*)h)[2*i+1] = __halves2bfloat162(h2, h3);
    ((__nv_bfloat162*)l)[2*i]   = __halves2bfloat162(l0, l1);
    ((__nv_bfloat162*)l)[2*i+1] = __halves2bfloat162(l2, l3);
}

// ---------------------------------------------------------------------------
// transpose+split: W[K,N] fp32 -> Th,Tl [N,K] bf16
// ---------------------------------------------------------------------------
__global__ void tsplit_kernel(const float* __restrict__ W,
                              __nv_bfloat16* __restrict__ Th,
                              __nv_bfloat16* __restrict__ Tl, int K, int N)
{
    __shared__ float ts[32][33];
    const int n0 = blockIdx.x * 32, k0 = blockIdx.y * 32;
    const int tx = threadIdx.x, ty = threadIdx.y;
    for (int i = ty; i < 32; i += 8)
        ts[i][tx] = W[(size_t)(k0 + i) * N + n0 + tx];
    __syncthreads();
    for (int i = ty; i < 32; i += 8) {
        float v = ts[tx][i];
        __nv_bfloat16 hv = __float2bfloat16(v);
        __nv_bfloat16 lv = __float2bfloat16(v - __bfloat162float(hv));
        size_t o = (size_t)(n0 + i) * K + k0 + tx;
        Th[o] = hv;
        Tl[o] = lv;
    }
}

// ---------------------------------------------------------------------------
// bf16x3 GEMM via mma.sync (unchanged from passing round)
// ---------------------------------------------------------------------------
#define BKG 32
#define SROW 80
#define TBYTES (128 * SROW)
#define BUFBYTES (4 * TBYTES)
#define GSMEM_BYTES (2 * BUFBYTES)

__device__ __forceinline__ void tile_cp(uint32_t sdst,
                                        const __nv_bfloat16* __restrict__ g,
                                        int ldk, int row0, int k0, int t)
{
    const char* gb = (const char*)(g + (size_t)row0 * ldk + k0);
    const size_t rs = (size_t)ldk * 2;
#pragma unroll
    for (int i = 0; i < 2; i++) {
        int idx = t + i * 256;
        int r = idx >> 2;
        int c = (idx & 3) << 4;
        cpa16(sdst + r * SROW + c, gb + (size_t)r * rs + c);
    }
}

__global__ __launch_bounds__(256)
void gemm_bf16x3(const __nv_bfloat16* __restrict__ Ah,
                 const __nv_bfloat16* __restrict__ Al,
                 const __nv_bfloat16* __restrict__ Bh,
                 const __nv_bfloat16* __restrict__ Bl,
                 const float* __restrict__ bias,
                 float* __restrict__ C, int M, int N, int K)
{
    extern __shared__ char sm[];
    const uint32_t sbase = smem_u32(sm);
    const int t = threadIdx.x;
    const int wid = t >> 5, lane = t & 31;
    const int wm = wid & 1, wn = wid >> 1;
    const int bm = blockIdx.y * 128, bn = blockIdx.x * 128;
    const int NT = K / BKG;

    float acc[4][4][4];
#pragma unroll
    for (int mt = 0; mt < 4; mt++)
#pragma unroll
        for (int nt = 0; nt < 4; nt++)
#pragma unroll
            for (int i = 0; i < 4; i++) acc[mt][nt][i] = 0.f;

    {
        uint32_t s0 = sbase;
        tile_cp(s0,              Ah, K, bm, 0, t);
        tile_cp(s0 + TBYTES,     Al, K, bm, 0, t);
        tile_cp(s0 + 2 * TBYTES, Bh, K, bn, 0, t);
        tile_cp(s0 + 3 * TBYTES, Bl, K, bn, 0, t);
        CP_COMMIT();
    }

    const int q = lane >> 3, r8 = lane & 7;
    const int arow = wm * 64 + (q & 1) * 8 + r8;
    const int acolb = ((q >> 1) * 8) * 2;
    const int t16 = lane & 15;
    const int brow = wn * 32 + (t16 & 7);
    const int bcolb = ((t16 >> 3) * 8) * 2;

    for (int kt = 0; kt < NT; kt++) {
        const uint32_t sb = sbase + (kt & 1) * BUFBYTES;
        if (kt + 1 < NT) {
            const uint32_t sn = sbase + ((kt + 1) & 1) * BUFBYTES;
            const int k0 = (kt + 1) * BKG;
            tile_cp(sn,              Ah, K, bm, k0, t);
            tile_cp(sn + TBYTES,     Al, K, bm, k0, t);
            tile_cp(sn + 2 * TBYTES, Bh, K, bn, k0, t);
            tile_cp(sn + 3 * TBYTES, Bl, K, bn, k0, t);
            CP_COMMIT();
            CP_WAIT(1);
        } else {
            CP_WAIT(0);
        }
        __syncthreads();

#pragma unroll
        for (int kk = 0; kk < 2; kk++) {
            const uint32_t abase = sb + arow * SROW + kk * 32 + acolb;
            const uint32_t bbase = sb + 2 * TBYTES + brow * SROW + kk * 32 + bcolb;
            uint32_t ah_[4][4], al_[4][4], bh_[4][2], bl_[4][2];
#pragma unroll
            for (int mt = 0; mt < 4; mt++) {
                ldmx4(abase + mt * 16 * SROW, ah_[mt]);
                ldmx4(abase + TBYTES + mt * 16 * SROW, al_[mt]);
            }
#pragma unroll
            for (int nt = 0; nt < 4; nt++) {
                ldmx2(bbase + nt * 8 * SROW, bh_[nt]);
                ldmx2(bbase + TBYTES + nt * 8 * SROW, bl_[nt]);
            }
#pragma unroll
            for (int mt = 0; mt < 4; mt++)
#pragma unroll
                for (int nt = 0; nt < 4; nt++) {
                    mma16816(acc[mt][nt], ah_[mt], bh_[nt]);
                    mma16816(acc[mt][nt], ah_[mt], bl_[nt]);
                    mma16816(acc[mt][nt], al_[mt], bh_[nt]);
                }
        }
        __syncthreads();
    }

    const int gid = lane >> 2, tid2 = (lane & 3) * 2;
#pragma unroll
    for (int mt = 0; mt < 4; mt++) {
        const int row = bm + wm * 64 + mt * 16 + gid;
#pragma unroll
        for (int nt = 0; nt < 4; nt++) {
            const int col = bn + wn * 32 + nt * 8 + tid2;
            float b0 = 0.f, b1 = 0.f;
            if (bias) { b0 = bias[col]; b1 = bias[col + 1]; }
            float2 v0 = make_float2(acc[mt][nt][0] + b0, acc[mt][nt][1] + b1);
            float2 v1 = make_float2(acc[mt][nt][2] + b0, acc[mt][nt][3] + b1);
            *(float2*)&C[(size_t)row * N + col] = v0;
            *(float2*)&C[(size_t)(row + 8) * N + col] = v1;
        }
    }
}

// ---------------------------------------------------------------------------
// RoPE in-place on x[B*L, H*D], optional output scale (folds 1/sqrt(D) into Q)
// ---------------------------------------------------------------------------
__global__ void rope_kernel(float* __restrict__ x, int H, float oscale)
{
    __shared__ float cs[64], sn[64];
    const int row = blockIdx.x;
    const int pos = row & (LL - 1);
    const int t = threadIdx.x;
    if (t < 64) {
        float e   = (float)(2 * t) * (1.0f / (float)DD);
        float inv = powf(1000000.0f, -e);
        float ang = (float)pos * inv;
        cs[t] = cosf(ang);
        sn[t] = sinf(ang);
    }
    __syncthreads();
    float* xr = x + (size_t)row * H * DD;
    for (int i = t; i < H * 64; i += blockDim.x) {
        int h = i >> 6;
        int d = i & 63;
        float x1 = xr[h * DD + d];
        float x2 = xr[h * DD + d + 64];
        float c = cs[d], s = sn[d];
        xr[h * DD + d]      = (x1 * c - x2 * s) * oscale;
        xr[h * DD + d + 64] = (x2 * c + x1 * s) * oscale;
    }
}

// ---------------------------------------------------------------------------
// Flash attention on tensor cores (mma.sync bf16x3), causal, GQA G=8.
// CTA = 128 q-rows x one (b,h). 8 warps x 16 q-rows. kv tiles of 64,
// cp.async double-buffered. Q fragments register-resident.
// ---------------------------------------------------------------------------
#define KROW 272                  // 128 bf16 = 256B + 16B pad
#define ATILE (64 * KROW)         // 17408
#define ABUF  (4 * ATILE)         // Kh,Kl,Vh,Vl = 69632
#define ASMEM (2 * ABUF)          // 139264

__global__ __launch_bounds__(256)
void attn_mma(const __nv_bfloat16* __restrict__ Qh,
              const __nv_bfloat16* __restrict__ Ql,
              const __nv_bfloat16* __restrict__ Kh,
              const __nv_bfloat16* __restrict__ Kl,
              const __nv_bfloat16* __restrict__ Vh,
              const __nv_bfloat16* __restrict__ Vl,
              float* __restrict__ o_out)
{
    extern __shared__ char sm[];
    const uint32_t sb = smem_u32(sm);
    const int t = threadIdx.x, w = t >> 5, lane = t & 31;
    const int qt = blockIdx.x;          // 0..15 (128-row q tiles)
    const int bh = blockIdx.y;          // 0..31
    const int b = bh >> 4, h = bh & 15, hk = h >> 3;
    const int q0 = qt * 128;

    // ---- Load Q tile (hi at sb, lo at sb + 128*KROW) via cp.async ----
    {
        const char* gqh = (const char*)(Qh + ((size_t)(b * LL + q0)) * (HQ * DD) + h * DD);
        const char* gql = (const char*)(Ql + ((size_t)(b * LL + q0)) * (HQ * DD) + h * DD);
#pragma unroll
        for (int i = 0; i < 8; i++) {
            int idx = t + i * 256;          // 0..2047
            int r = idx >> 4;               // 0..127
            int c = (idx & 15) << 4;        // 0..240
            cpa16(sb + r * KROW + c,               gqh + (size_t)r * 4096 + c);
            cpa16(sb + 128 * KROW + r * KROW + c,  gql + (size_t)r * 4096 + c);
        }
        CP_COMMIT();
        CP_WAIT(0);
        __syncthreads();
    }

    // ---- ldmatrix Q fragments into registers ----
    uint32_t qfh[8][4], qfl[8][4];
    {
        const int qq = lane >> 3, r8 = lane & 7;
        const uint32_t qaddr = sb + (w * 16 + (qq & 1) * 8 + r8) * KROW + (qq >> 1) * 16;
#pragma unroll
        for (int c = 0; c < 8; c++) {
            ldmx4(qaddr + c * 32, qfh[c]);
            ldmx4(qaddr + 128 * KROW + c * 32, qfl[c]);
        }
    }
    __syncthreads();   // Q smem area now reusable as KV buffer 0

    float oacc[16][4];
#pragma unroll
    for (int v = 0; v < 16; v++)
#pragma unroll
        for (int e = 0; e < 4; e++) oacc[v][e] = 0.f;
    float m0 = -1e30f, m1 = -1e30f, l0 = 0.f, l1 = 0.f;

    const int NT = 2 * qt + 2;
    const size_t kvrow = (size_t)(HKV * DD) * 2;   // 512 B

    // prologue: kv tile 0 -> buffer 0
    {
        const char* s0 = (const char*)(Kh + ((size_t)(b * LL)) * (HKV * DD) + hk * DD);
        const char* s1 = (const char*)(Kl + ((size_t)(b * LL)) * (HKV * DD) + hk * DD);
        const char* s2 = (const char*)(Vh + ((size_t)(b * LL)) * (HKV * DD) + hk * DD);
        const char* s3 = (const char*)(Vl + ((size_t)(b * LL)) * (HKV * DD) + hk * DD);
        const char* srcs[4] = {s0, s1, s2, s3};
#pragma unroll
        for (int i = 0; i < 16; i++) {
            int idx = t + i * 256;
            int mat = idx >> 10;
            int r = (idx >> 4) & 63;
            int c = (idx & 15) << 4;
            cpa16(sb + mat * ATILE + r * KROW + c, srcs[mat] + (size_t)r * kvrow + c);
        }
        CP_COMMIT();
    }

    const int g = lane >> 2;
    const int row0 = q0 + w * 16 + g;          // lane's first q row
    const int colq = (lane & 3) * 2;

    for (int kt = 0; kt < NT; kt++) {
        if (kt + 1 < NT) {
            const uint32_t nb = sb + ((kt + 1) & 1) * ABUF;
            const size_t roff = ((size_t)(b * LL + (kt + 1) * 64)) * (HKV * DD) + hk * DD;
            const char* s0 = (const char*)(Kh + roff);
            const char* s1 = (const char*)(Kl + roff);
            const char* s2 = (const char*)(Vh + roff);
            const char* s3 = (const char*)(Vl + roff);
            const char* srcs[4] = {s0, s1, s2, s3};
#pragma unroll
            for (int i = 0; i < 16; i++) {
                int idx = t + i * 256;
                int mat = idx >> 10;
                int r = (idx >> 4) & 63;
                int c = (idx & 15) << 4;
                cpa16(nb + mat * ATILE + r * KROW + c, srcs[mat] + (size_t)r * kvrow + c);
            }
            CP_COMMIT();
            CP_WAIT(1);
        } else {
            CP_WAIT(0);
        }
        __syncthreads();

        const uint32_t kb = sb + (kt & 1) * ABUF;
        const int kv0 = kt * 64;

        // ---- S = Q K^T (bf16x3) ----
        float s_[8][4];
#pragma unroll
        for (int j = 0; j < 8; j++)
#pragma unroll
            for (int e = 0; e < 4; e++) s_[j][e] = 0.f;

        const uint32_t kaddr = kb + (lane & 7) * KROW + (lane >> 3) * 16;
#pragma unroll
        for (int c32 = 0; c32 < 4; c32++) {
#pragma unroll
            for (int j = 0; j < 8; j++) {
                uint32_t kfh[4], kfl[4];
                ldmx4(kaddr + j * 8 * KROW + c32 * 64, kfh);
                ldmx4(kaddr + ATILE + j * 8 * KROW + c32 * 64, kfl);
                uint32_t bh0[2] = {kfh[0], kfh[1]}, bh1[2] = {kfh[2], kfh[3]};
                uint32_t bl0[2] = {kfl[0], kfl[1]}, bl1[2] = {kfl[2], kfl[3]};
                mma16816(s_[j], qfh[2 * c32],     bh0);
                mma16816(s_[j], qfh[2 * c32 + 1], bh1);
                mma16816(s_[j], qfh[2 * c32],     bl0);
                mma16816(s_[j], qfh[2 * c32 + 1], bl1);
                mma16816(s_[j], qfl[2 * c32],     bh0);
                mma16816(s_[j], qfl[2 * c32 + 1], bh1);
            }
        }

        // ---- causal mask ----
#pragma unroll
        for (int j = 0; j < 8; j++) {
            int c0 = kv0 + 8 * j + colq;
            if (c0 > row0)     s_[j][0] = -1e30f;
            if (c0 + 1 > row0) s_[j][1] = -1e30f;
            if (c0 > row0 + 8)     s_[j][2] = -1e30f;
            if (c0 + 1 > row0 + 8) s_[j][3] = -1e30f;
        }

        // ---- online softmax ----
        float mx0 = -1e30f, mx1 = -1e30f;
#pragma unroll
        for (int j = 0; j < 8; j++) {
            mx0 = fmaxf(mx0, fmaxf(s_[j][0], s_[j][1]));
            mx1 = fmaxf(mx1, fmaxf(s_[j][2], s_[j][3]));
        }
        mx0 = fmaxf(mx0, __shfl_xor_sync(0xffffffffu, mx0, 1));
        mx0 = fmaxf(mx0, __shfl_xor_sync(0xffffffffu, mx0, 2));
        mx1 = fmaxf(mx1, __shfl_xor_sync(0xffffffffu, mx1, 1));
        mx1 = fmaxf(mx1, __shfl_xor_sync(0xffffffffu, mx1, 2));
        const float m0n = fmaxf(m0, mx0), m1n = fmaxf(m1, mx1);
        const float cr0 = __expf(m0 - m0n), cr1 = __expf(m1 - m1n);
        float sum0 = 0.f, sum1 = 0.f;
#pragma unroll
        for (int j = 0; j < 8; j++) {
            s_[j][0] = __expf(s_[j][0] - m0n); sum0 += s_[j][0];
            s_[j][1] = __expf(s_[j][1] - m0n); sum0 += s_[j][1];
            s_[j][2] = __expf(s_[j][2] - m1n); sum1 += s_[j][2];
            s_[j][3] = __expf(s_[j][3] - m1n); sum1 += s_[j][3];
        }
        sum0 += __shfl_xor_sync(0xffffffffu, sum0, 1);
        sum0 += __shfl_xor_sync(0xffffffffu, sum0, 2);
        sum1 += __shfl_xor_sync(0xffffffffu, sum1, 1);
        sum1 += __shfl_xor_sync(0xffffffffu, sum1, 2);
        l0 = l0 * cr0 + sum0;  m0 = m0n;
        l1 = l1 * cr1 + sum1;  m1 = m1n;
#pragma unroll
        for (int v = 0; v < 16; v++) {
            oacc[v][0] *= cr0; oacc[v][1] *= cr0;
            oacc[v][2] *= cr1; oacc[v][3] *= cr1;
        }

        // ---- pack P into A-fragments (hi/lo) ----
        uint32_t ph01[8], ph23[8], pl01[8], pl23[8];
#pragma unroll
        for (int j = 0; j < 8; j++) {
            __nv_bfloat162 h01 = __floats2bfloat162_rn(s_[j][0], s_[j][1]);
            __nv_bfloat162 h23 = __floats2bfloat162_rn(s_[j][2], s_[j][3]);
            ph01[j] = *(uint32_t*)&h01;
            ph23[j] = *(uint32_t*)&h23;
            __nv_bfloat162 lo01 = __floats2bfloat162_rn(
                s_[j][0] - __bfloat162float(h01.x),
                s_[j][1] - __bfloat162float(h01.y));
            __nv_bfloat162 lo23 = __floats2bfloat162_rn(
                s_[j][2] - __bfloat162float(h23.x),
                s_[j][3] - __bfloat162float(h23.y));
            pl01[j] = *(uint32_t*)&lo01;
            pl23[j] = *(uint32_t*)&lo23;
        }

        // ---- O += P V (bf16x3); V via ldmatrix.trans ----
        const uint32_t vaddr = kb + 2 * ATILE + lane * KROW;
#pragma unroll
        for (int t32 = 0; t32 < 2; t32++) {
            uint32_t Ah0[4] = {ph01[4*t32],   ph23[4*t32],   ph01[4*t32+1], ph23[4*t32+1]};
            uint32_t Ah1[4] = {ph01[4*t32+2], ph23[4*t32+2], ph01[4*t32+3], ph23[4*t32+3]};
            uint32_t Al0[4] = {pl01[4*t32],   pl23[4*t32],   pl01[4*t32+1], pl23[4*t32+1]};
            uint32_t Al1[4] = {pl01[4*t32+2], pl23[4*t32+2], pl01[4*t32+3], pl23[4*t32+3]};
#pragma unroll
            for (int v = 0; v < 16; v++) {
                uint32_t vfh[4], vfl[4];
                ldmx4t(vaddr + t32 * 32 * KROW + v * 16, vfh);
                ldmx4t(vaddr + ATILE + t32 * 32 * KROW + v * 16, vfl);
                uint32_t bh0[2] = {vfh[0], vfh[1]}, bh1[2] = {vfh[2], vfh[3]};
                uint32_t bl0[2] = {vfl[0], vfl[1]}, bl1[2] = {vfl[2], vfl[3]};
                mma16816(oacc[v], Ah0, bh0);
                mma16816(oacc[v], Ah1, bh1);
                mma16816(oacc[v], Ah0, bl0);
                mma16816(oacc[v], Ah1, bl1);
                mma16816(oacc[v], Al0, bh0);
                mma16816(oacc[v], Al1, bh1);
            }
        }
        __syncthreads();   // done reading this buffer before next prefetch wave
    }

    // ---- epilogue ----
    const float inv0 = 1.0f / l0, inv1 = 1.0f / l1;
    const size_t r0off = ((size_t)(b * LL + q0 + w * 16 + g)) * (HQ * DD) + h * DD + colq;
    const size_t r1off = r0off + 8 * (size_t)(HQ * DD);
#pragma unroll
    for (int v = 0; v < 16; v++) {
        float2 o0 = make_float2(oacc[v][0] * inv0, oacc[v][1] * inv0);
        float2 o1 = make_float2(oacc[v][2] * inv1, oacc[v][3] * inv1);
        *(float2*)&o_out[r0off + 8 * v] = o0;
        *(float2*)&o_out[r1off + 8 * v] = o1;
    }
}

// ---------------------------------------------------------------------------
// Launch
// ---------------------------------------------------------------------------
extern "C" void kernel_launch(void* const* d_in, const int* in_sizes, int n_in,
                              void* d_out, int out_size)
{
    const float* X  = (const float*)d_in[0];
    const float* Wq = (const float*)d_in[1];
    const float* bq = (const float*)d_in[2];
    const float* Wk = (const float*)d_in[3];
    const float* bk = (const float*)d_in[4];
    const float* Wv = (const float*)d_in[5];
    const float* bv = (const float*)d_in[6];
    const float* Wo = (const float*)d_in[7];
    float* out = (float*)d_out;

    float *qp, *kp, *vp, *ap;
    __nv_bfloat16 *ah, *al, *kh2, *kl2, *vh2, *vl2;
    __nv_bfloat16 *wqh, *wql, *wkh, *wkl, *wvh, *wvl, *woh, *wol;
    cudaGetSymbolAddress((void**)&qp, g_q);
    cudaGetSymbolAddress((void**)&kp, g_k);
    cudaGetSymbolAddress((void**)&vp, g_v);
    cudaGetSymbolAddress((void**)&ap, g_attn);
    cudaGetSymbolAddress((void**)&ah, g_ah);
    cudaGetSymbolAddress((void**)&al, g_al);
    cudaGetSymbolAddress((void**)&kh2, g_kh2);
    cudaGetSymbolAddress((void**)&kl2, g_kl2);
    cudaGetSymbolAddress((void**)&vh2, g_vh2);
    cudaGetSymbolAddress((void**)&vl2, g_vl2);
    cudaGetSymbolAddress((void**)&wqh, g_wqh);
    cudaGetSymbolAddress((void**)&wql, g_wql);
    cudaGetSymbolAddress((void**)&wkh, g_wkh);
    cudaGetSymbolAddress((void**)&wkl, g_wkl);
    cudaGetSymbolAddress((void**)&wvh, g_wvh);
    cudaGetSymbolAddress((void**)&wvl, g_wvl);
    cudaGetSymbolAddress((void**)&woh, g_woh);
    cudaGetSymbolAddress((void**)&wol, g_wol);

    cudaFuncSetAttribute(gemm_bf16x3,
                         cudaFuncAttributeMaxDynamicSharedMemorySize, GSMEM_BYTES);
    cudaFuncSetAttribute(attn_mma,
                         cudaFuncAttributeMaxDynamicSharedMemorySize, ASMEM);

    const int n4x = (int)((size_t)MROWS * EE / 4);
    const int n4kv = (int)((size_t)MROWS * HKV * DD / 4);
    const float scale = 0.08838834764831845f;   // 1/sqrt(128)

    // Split X + transpose/split weights
    split_kernel<<<(n4x + 255) / 256, 256>>>(X, ah, al, n4x);
    tsplit_kernel<<<dim3((HQ*DD)/32, EE/32), dim3(32, 8)>>>(Wq, wqh, wql, EE, HQ*DD);
    tsplit_kernel<<<dim3((HKV*DD)/32, EE/32), dim3(32, 8)>>>(Wk, wkh, wkl, EE, HKV*DD);
    tsplit_kernel<<<dim3((HKV*DD)/32, EE/32), dim3(32, 8)>>>(Wv, wvh, wvl, EE, HKV*DD);
    tsplit_kernel<<<dim3(EE/32, (HQ*DD)/32), dim3(32, 8)>>>(Wo, woh, wol, HQ*DD, EE);

    // QKV projections
    gemm_bf16x3<<<dim3((HQ*DD)/128, MROWS/128), 256, GSMEM_BYTES>>>(
        ah, al, wqh, wql, bq, qp, MROWS, HQ*DD, EE);
    gemm_bf16x3<<<dim3((HKV*DD)/128, MROWS/128), 256, GSMEM_BYTES>>>(
        ah, al, wkh, wkl, bk, kp, MROWS, HKV*DD, EE);
    gemm_bf16x3<<<dim3((HKV*DD)/128, MROWS/128), 256, GSMEM_BYTES>>>(
        ah, al, wvh, wvl, bv, vp, MROWS, HKV*DD, EE);

    // RoPE (scale folded into Q)
    rope_kernel<<<MROWS, 256>>>(qp, HQ, scale);
    rope_kernel<<<MROWS, 256>>>(kp, HKV, 1.0f);

    // Split Q/K/V to bf16 hi/lo (Q reuses X split buffers — gemms done)
    split_kernel<<<(n4x + 255) / 256, 256>>>(qp, ah, al, n4x);
    split_kernel<<<(n4kv + 255) / 256, 256>>>(kp, kh2, kl2, n4kv);
    split_kernel<<<(n4kv + 255) / 256, 256>>>(vp, vh2, vl2, n4kv);

    // Attention on tensor cores
    attn_mma<<<dim3(LL / 128, BB * HQ), 256, ASMEM>>>(ah, al, kh2, kl2, vh2, vl2, ap);

    // Output projection
    split_kernel<<<(n4x + 255) / 256, 256>>>(ap, ah, al, n4x);
    gemm_bf16x3<<<dim3(EE/128, MROWS/128), 256, GSMEM_BYTES>>>(
        ah, al, woh, wol, nullptr, out, MROWS, EE, EE);
}

// round 10
// speedup vs baseline: 1.6515x; 1.0006x over previous
#include <cuda_runtime.h>
#include <cuda_bf16.h>
#include <cstdint>
#include <cstddef>

// Problem constants
#define BB 2
#define LL 2048
#define EE 2048
#define HQ 16
#define HKV 2
#define DD 128
#define MROWS (BB*LL)   // 4096

// ---------------------------------------------------------------------------
// Scratch (device globals — no allocations allowed)
// ---------------------------------------------------------------------------
__device__ float g_q[(size_t)MROWS * HQ * DD];     // 32 MB
__device__ float g_k[(size_t)MROWS * HKV * DD];    // 4 MB
__device__ float g_v[(size_t)MROWS * HKV * DD];    // 4 MB
__device__ float g_attn[(size_t)MROWS * HQ * DD];  // 32 MB

// bf16 split activations (X -> gemms; then Q hi/lo; then attn-out)
__device__ __nv_bfloat16 g_ah[(size_t)MROWS * EE];
__device__ __nv_bfloat16 g_al[(size_t)MROWS * EE];
// bf16 split K / V (post-rope for K)
__device__ __nv_bfloat16 g_kh2[(size_t)MROWS * HKV * DD];
__device__ __nv_bfloat16 g_kl2[(size_t)MROWS * HKV * DD];
__device__ __nv_bfloat16 g_vh2[(size_t)MROWS * HKV * DD];
__device__ __nv_bfloat16 g_vl2[(size_t)MROWS * HKV * DD];
// bf16 split transposed weights [N, K] (K-major)
__device__ __nv_bfloat16 g_wqh[(size_t)(HQ*DD) * EE];
__device__ __nv_bfloat16 g_wql[(size_t)(HQ*DD) * EE];
__device__ __nv_bfloat16 g_wkh[(size_t)(HKV*DD) * EE];
__device__ __nv_bfloat16 g_wkl[(size_t)(HKV*DD) * EE];
__device__ __nv_bfloat16 g_wvh[(size_t)(HKV*DD) * EE];
__device__ __nv_bfloat16 g_wvl[(size_t)(HKV*DD) * EE];
__device__ __nv_bfloat16 g_woh[(size_t)EE * (HQ*DD)];
__device__ __nv_bfloat16 g_wol[(size_t)EE * (HQ*DD)];

// ---------------------------------------------------------------------------
// PTX helpers (base-ISA: cp.async / ldmatrix / mma.sync)
// ---------------------------------------------------------------------------
__device__ __forceinline__ uint32_t smem_u32(const void* p) {
    uint32_t a;
    asm("{ .reg .u64 t; cvta.to.shared.u64 t, %1; cvt.u32.u64 %0, t; }"
        : "=r"(a) : "l"(p));
    return a;
}

__device__ __forceinline__ void cpa16(uint32_t d, const void* s) {
    asm volatile("cp.async.cg.shared.global [%0], [%1], 16;" :: "r"(d), "l"(s));
}
#define CP_COMMIT() asm volatile("cp.async.commit_group;")
#define CP_WAIT(n)  asm volatile("cp.async.wait_group %0;" :: "n"(n))

__device__ __forceinline__ void ldmx4(uint32_t a, uint32_t r[4]) {
    asm volatile("ldmatrix.sync.aligned.m8n8.x4.shared.b16 {%0,%1,%2,%3}, [%4];"
                 : "=r"(r[0]), "=r"(r[1]), "=r"(r[2]), "=r"(r[3]) : "r"(a));
}
__device__ __forceinline__ void ldmx2(uint32_t a, uint32_t r[2]) {
    asm volatile("ldmatrix.sync.aligned.m8n8.x2.shared.b16 {%0,%1}, [%2];"
                 : "=r"(r[0]), "=r"(r[1]) : "r"(a));
}
__device__ __forceinline__ void ldmx4t(uint32_t a, uint32_t r[4]) {
    asm volatile("ldmatrix.sync.aligned.m8n8.x4.trans.shared.b16 {%0,%1,%2,%3}, [%4];"
                 : "=r"(r[0]), "=r"(r[1]), "=r"(r[2]), "=r"(r[3]) : "r"(a));
}

__device__ __forceinline__ void mma16816(float c[4], const uint32_t a[4],
                                         const uint32_t b[2]) {
    asm volatile(
        "mma.sync.aligned.m16n8k16.row.col.f32.bf16.bf16.f32 "
        "{%0,%1,%2,%3}, {%4,%5,%6,%7}, {%8,%9}, {%0,%1,%2,%3};"
        : "+f"(c[0]), "+f"(c[1]), "+f"(c[2]), "+f"(c[3])
        : "r"(a[0]), "r"(a[1]), "r"(a[2]), "r"(a[3]), "r"(b[0]), "r"(b[1]));
}

// ---------------------------------------------------------------------------
// split: fp32 -> bf16 hi + bf16 lo
// ---------------------------------------------------------------------------
__global__ void split_kernel(const float* __restrict__ x,
                             __nv_bfloat16* __restrict__ h,
                             __nv_bfloat16* __restrict__ l, int n4)
{
    int i = blockIdx.x * blockDim.x + threadIdx.x;
    if (i >= n4) return;
    float4 v = ((const float4*)x)[i];
    __nv_bfloat16 h0 = __float2bfloat16(v.x);
    __nv_bfloat16 h1 = __float2bfloat16(v.y);
    __nv_bfloat16 h2 = __float2bfloat16(v.z);
    __nv_bfloat16 h3 = __float2bfloat16(v.w);
    __nv_bfloat16 l0 = __float2bfloat16(v.x - __bfloat162float(h0));
    __nv_bfloat16 l1 = __float2bfloat16(v.y - __bfloat162float(h1));
    __nv_bfloat16 l2 = __float2bfloat16(v.z - __bfloat162float(h2));
    __nv_bfloat16 l3 = __float2bfloat16(v.w - __bfloat162float(h3));
    ((__nv_bfloat162*)h)[2*i]   = __halves2bfloat162(h0, h1);
    ((__nv_bfloat162*)h)[2*i+1] = __halves2bfloat162(h2, h3);
    ((__nv_bfloat162*)l)[2*i]   = __halves2bfloat162(l0, l1);
    ((__nv_bfloat162*)l)[2*i+1] = __halves2bfloat162(l2, l3);
}

// ---------------------------------------------------------------------------
// transpose+split: W[K,N] fp32 -> Th,Tl [N,K] bf16
// ---------------------------------------------------------------------------
__global__ void tsplit_kernel(const float* __restrict__ W,
                              __nv_bfloat16* __restrict__ Th,
                              __nv_bfloat16* __restrict__ Tl, int K, int N)
{
    __shared__ float ts[32][33];
    const int n0 = blockIdx.x * 32, k0 = blockIdx.y * 32;
    const int tx = threadIdx.x, ty = threadIdx.y;
    for (int i = ty; i < 32; i += 8)
        ts[i][tx] = W[(size_t)(k0 + i) * N + n0 + tx];
    __syncthreads();
    for (int i = ty; i < 32; i += 8) {
        float v = ts[tx][i];
        __nv_bfloat16 hv = __float2bfloat16(v);
        __nv_bfloat16 lv = __float2bfloat16(v - __bfloat162float(hv));
        size_t o = (size_t)(n0 + i) * K + k0 + tx;
        Th[o] = hv;
        Tl[o] = lv;
    }
}

// ---------------------------------------------------------------------------
// bf16x3 GEMM via mma.sync (unchanged from passing round)
// ---------------------------------------------------------------------------
#define BKG 32
#define SROW 80
#define TBYTES (128 * SROW)
#define BUFBYTES (4 * TBYTES)
#define GSMEM_BYTES (2 * BUFBYTES)

__device__ __forceinline__ void tile_cp(uint32_t sdst,
                                        const __nv_bfloat16* __restrict__ g,
                                        int ldk, int row0, int k0, int t)
{
    const char* gb = (const char*)(g + (size_t)row0 * ldk + k0);
    const size_t rs = (size_t)ldk * 2;
#pragma unroll
    for (int i = 0; i < 2; i++) {
        int idx = t + i * 256;
        int r = idx >> 2;
        int c = (idx & 3) << 4;
        cpa16(sdst + r * SROW + c, gb + (size_t)r * rs + c);
    }
}

__global__ __launch_bounds__(256)
void gemm_bf16x3(const __nv_bfloat16* __restrict__ Ah,
                 const __nv_bfloat16* __restrict__ Al,
                 const __nv_bfloat16* __restrict__ Bh,
                 const __nv_bfloat16* __restrict__ Bl,
                 const float* __restrict__ bias,
                 float* __restrict__ C, int M, int N, int K)
{
    extern __shared__ char sm[];
    const uint32_t sbase = smem_u32(sm);
    const int t = threadIdx.x;
    const int wid = t >> 5, lane = t & 31;
    const int wm = wid & 1, wn = wid >> 1;
    const int bm = blockIdx.y * 128, bn = blockIdx.x * 128;
    const int NT = K / BKG;

    float acc[4][4][4];
#pragma unroll
    for (int mt = 0; mt < 4; mt++)
#pragma unroll
        for (int nt = 0; nt < 4; nt++)
#pragma unroll
            for (int i = 0; i < 4; i++) acc[mt][nt][i] = 0.f;

    {
        uint32_t s0 = sbase;
        tile_cp(s0,              Ah, K, bm, 0, t);
        tile_cp(s0 + TBYTES,     Al, K, bm, 0, t);
        tile_cp(s0 + 2 * TBYTES, Bh, K, bn, 0, t);
        tile_cp(s0 + 3 * TBYTES, Bl, K, bn, 0, t);
        CP_COMMIT();
    }

    const int q = lane >> 3, r8 = lane & 7;
    const int arow = wm * 64 + (q & 1) * 8 + r8;
    const int acolb = ((q >> 1) * 8) * 2;
    const int t16 = lane & 15;
    const int brow = wn * 32 + (t16 & 7);
    const int bcolb = ((t16 >> 3) * 8) * 2;

    for (int kt = 0; kt < NT; kt++) {
        const uint32_t sb = sbase + (kt & 1) * BUFBYTES;
        if (kt + 1 < NT) {
            const uint32_t sn = sbase + ((kt + 1) & 1) * BUFBYTES;
            const int k0 = (kt + 1) * BKG;
            tile_cp(sn,              Ah, K, bm, k0, t);
            tile_cp(sn + TBYTES,     Al, K, bm, k0, t);
            tile_cp(sn + 2 * TBYTES, Bh, K, bn, k0, t);
            tile_cp(sn + 3 * TBYTES, Bl, K, bn, k0, t);
            CP_COMMIT();
            CP_WAIT(1);
        } else {
            CP_WAIT(0);
        }
        __syncthreads();

#pragma unroll
        for (int kk = 0; kk < 2; kk++) {
            const uint32_t abase = sb + arow * SROW + kk * 32 + acolb;
            const uint32_t bbase = sb + 2 * TBYTES + brow * SROW + kk * 32 + bcolb;
            uint32_t ah_[4][4], al_[4][4], bh_[4][2], bl_[4][2];
#pragma unroll
            for (int mt = 0; mt < 4; mt++) {
                ldmx4(abase + mt * 16 * SROW, ah_[mt]);
                ldmx4(abase + TBYTES + mt * 16 * SROW, al_[mt]);
            }
#pragma unroll
            for (int nt = 0; nt < 4; nt++) {
                ldmx2(bbase + nt * 8 * SROW, bh_[nt]);
                ldmx2(bbase + TBYTES + nt * 8 * SROW, bl_[nt]);
            }
#pragma unroll
            for (int mt = 0; mt < 4; mt++)
#pragma unroll
                for (int nt = 0; nt < 4; nt++) {
                    mma16816(acc[mt][nt], ah_[mt], bh_[nt]);
                    mma16816(acc[mt][nt], ah_[mt], bl_[nt]);
                    mma16816(acc[mt][nt], al_[mt], bh_[nt]);
                }
        }
        __syncthreads();
    }

    const int gid = lane >> 2, tid2 = (lane & 3) * 2;
#pragma unroll
    for (int mt = 0; mt < 4; mt++) {
        const int row = bm + wm * 64 + mt * 16 + gid;
#pragma unroll
        for (int nt = 0; nt < 4; nt++) {
            const int col = bn + wn * 32 + nt * 8 + tid2;
            float b0 = 0.f, b1 = 0.f;
            if (bias) { b0 = bias[col]; b1 = bias[col + 1]; }
            float2 v0 = make_float2(acc[mt][nt][0] + b0, acc[mt][nt][1] + b1);
            float2 v1 = make_float2(acc[mt][nt][2] + b0, acc[mt][nt][3] + b1);
            *(float2*)&C[(size_t)row * N + col] = v0;
            *(float2*)&C[(size_t)(row + 8) * N + col] = v1;
        }
    }
}

// ---------------------------------------------------------------------------
// RoPE in-place on x[B*L, H*D], optional output scale (folds 1/sqrt(D) into Q)
// ---------------------------------------------------------------------------
__global__ void rope_kernel(float* __restrict__ x, int H, float oscale)
{
    __shared__ float cs[64], sn[64];
    const int row = blockIdx.x;
    const int pos = row & (LL - 1);
    const int t = threadIdx.x;
    if (t < 64) {
        float e   = (float)(2 * t) * (1.0f / (float)DD);
        float inv = powf(1000000.0f, -e);
        float ang = (float)pos * inv;
        cs[t] = cosf(ang);
        sn[t] = sinf(ang);
    }
    __syncthreads();
    float* xr = x + (size_t)row * H * DD;
    for (int i = t; i < H * 64; i += blockDim.x) {
        int h = i >> 6;
        int d = i & 63;
        float x1 = xr[h * DD + d];
        float x2 = xr[h * DD + d + 64];
        float c = cs[d], s = sn[d];
        xr[h * DD + d]      = (x1 * c - x2 * s) * oscale;
        xr[h * DD + d + 64] = (x2 * c + x1 * s) * oscale;
    }
}

// ---------------------------------------------------------------------------
// Flash attention on tensor cores (mma.sync bf16x3), causal, GQA G=8.
// CTA = 128 q-rows x one (b,h). 8 warps x 16 q-rows. kv tiles of 64,
// cp.async double-buffered. Q fragments register-resident.
// ---------------------------------------------------------------------------
#define KROW 272                  // 128 bf16 = 256B + 16B pad
#define ATILE (64 * KROW)         // 17408
#define ABUF  (4 * ATILE)         // Kh,Kl,Vh,Vl = 69632
#define ASMEM (2 * ABUF)          // 139264

__global__ __launch_bounds__(256)
void attn_mma(const __nv_bfloat16* __restrict__ Qh,
              const __nv_bfloat16* __restrict__ Ql,
              const __nv_bfloat16* __restrict__ Kh,
              const __nv_bfloat16* __restrict__ Kl,
              const __nv_bfloat16* __restrict__ Vh,
              const __nv_bfloat16* __restrict__ Vl,
              float* __restrict__ o_out)
{
    extern __shared__ char sm[];
    const uint32_t sb = smem_u32(sm);
    const int t = threadIdx.x, w = t >> 5, lane = t & 31;
    const int qt = blockIdx.x;          // 0..15 (128-row q tiles)
    const int bh = blockIdx.y;          // 0..31
    const int b = bh >> 4, h = bh & 15, hk = h >> 3;
    const int q0 = qt * 128;

    // ---- Load Q tile (hi at sb, lo at sb + 128*KROW) via cp.async ----
    {
        const char* gqh = (const char*)(Qh + ((size_t)(b * LL + q0)) * (HQ * DD) + h * DD);
        const char* gql = (const char*)(Ql + ((size_t)(b * LL + q0)) * (HQ * DD) + h * DD);
#pragma unroll
        for (int i = 0; i < 8; i++) {
            int idx = t + i * 256;          // 0..2047
            int r = idx >> 4;               // 0..127
            int c = (idx & 15) << 4;        // 0..240
            cpa16(sb + r * KROW + c,               gqh + (size_t)r * 4096 + c);
            cpa16(sb + 128 * KROW + r * KROW + c,  gql + (size_t)r * 4096 + c);
        }
        CP_COMMIT();
        CP_WAIT(0);
        __syncthreads();
    }

    // ---- ldmatrix Q fragments into registers ----
    uint32_t qfh[8][4], qfl[8][4];
    {
        const int qq = lane >> 3, r8 = lane & 7;
        const uint32_t qaddr = sb + (w * 16 + (qq & 1) * 8 + r8) * KROW + (qq >> 1) * 16;
#pragma unroll
        for (int c = 0; c < 8; c++) {
            ldmx4(qaddr + c * 32, qfh[c]);
            ldmx4(qaddr + 128 * KROW + c * 32, qfl[c]);
        }
    }
    __syncthreads();   // Q smem area now reusable as KV buffer 0

    float oacc[16][4];
#pragma unroll
    for (int v = 0; v < 16; v++)
#pragma unroll
        for (int e = 0; e < 4; e++) oacc[v][e] = 0.f;
    float m0 = -1e30f, m1 = -1e30f, l0 = 0.f, l1 = 0.f;

    const int NT = 2 * qt + 2;
    const size_t kvrow = (size_t)(HKV * DD) * 2;   // 512 B

    // prologue: kv tile 0 -> buffer 0
    {
        const char* s0 = (const char*)(Kh + ((size_t)(b * LL)) * (HKV * DD) + hk * DD);
        const char* s1 = (const char*)(Kl + ((size_t)(b * LL)) * (HKV * DD) + hk * DD);
        const char* s2 = (const char*)(Vh + ((size_t)(b * LL)) * (HKV * DD) + hk * DD);
        const char* s3 = (const char*)(Vl + ((size_t)(b * LL)) * (HKV * DD) + hk * DD);
        const char* srcs[4] = {s0, s1, s2, s3};
#pragma unroll
        for (int i = 0; i < 16; i++) {
            int idx = t + i * 256;
            int mat = idx >> 10;
            int r = (idx >> 4) & 63;
            int c = (idx & 15) << 4;
            cpa16(sb + mat * ATILE + r * KROW + c, srcs[mat] + (size_t)r * kvrow + c);
        }
        CP_COMMIT();
    }

    const int g = lane >> 2;
    const int row0 = q0 + w * 16 + g;          // lane's first q row
    const int colq = (lane & 3) * 2;

    for (int kt = 0; kt < NT; kt++) {
        if (kt + 1 < NT) {
            const uint32_t nb = sb + ((kt + 1) & 1) * ABUF;
            const size_t roff = ((size_t)(b * LL + (kt + 1) * 64)) * (HKV * DD) + hk * DD;
            const char* s0 = (const char*)(Kh + roff);
            const char* s1 = (const char*)(Kl + roff);
            const char* s2 = (const char*)(Vh + roff);
            const char* s3 = (const char*)(Vl + roff);
            const char* srcs[4] = {s0, s1, s2, s3};
#pragma unroll
            for (int i = 0; i < 16; i++) {
                int idx = t + i * 256;
                int mat = idx >> 10;
                int r = (idx >> 4) & 63;
                int c = (idx & 15) << 4;
                cpa16(nb + mat * ATILE + r * KROW + c, srcs[mat] + (size_t)r * kvrow + c);
            }
            CP_COMMIT();
            CP_WAIT(1);
        } else {
            CP_WAIT(0);
        }
        __syncthreads();

        const uint32_t kb = sb + (kt & 1) * ABUF;
        const int kv0 = kt * 64;

        // ---- S = Q K^T (bf16x3) ----
        float s_[8][4];
#pragma unroll
        for (int j = 0; j < 8; j++)
#pragma unroll
            for (int e = 0; e < 4; e++) s_[j][e] = 0.f;

        const uint32_t kaddr = kb + (lane & 7) * KROW + (lane >> 3) * 16;
#pragma unroll
        for (int c32 = 0; c32 < 4; c32++) {
#pragma unroll
            for (int j = 0; j < 8; j++) {
                uint32_t kfh[4], kfl[4];
                ldmx4(kaddr + j * 8 * KROW + c32 * 64, kfh);
                ldmx4(kaddr + ATILE + j * 8 * KROW + c32 * 64, kfl);
                uint32_t bh0[2] = {kfh[0], kfh[1]}, bh1[2] = {kfh[2], kfh[3]};
                uint32_t bl0[2] = {kfl[0], kfl[1]}, bl1[2] = {kfl[2], kfl[3]};
                mma16816(s_[j], qfh[2 * c32],     bh0);
                mma16816(s_[j], qfh[2 * c32 + 1], bh1);
                mma16816(s_[j], qfh[2 * c32],     bl0);
                mma16816(s_[j], qfh[2 * c32 + 1], bl1);
                mma16816(s_[j], qfl[2 * c32],     bh0);
                mma16816(s_[j], qfl[2 * c32 + 1], bh1);
            }
        }

        // ---- causal mask ----
#pragma unroll
        for (int j = 0; j < 8; j++) {
            int c0 = kv0 + 8 * j + colq;
            if (c0 > row0)     s_[j][0] = -1e30f;
            if (c0 + 1 > row0) s_[j][1] = -1e30f;
            if (c0 > row0 + 8)     s_[j][2] = -1e30f;
            if (c0 + 1 > row0 + 8) s_[j][3] = -1e30f;
        }

        // ---- online softmax ----
        float mx0 = -1e30f, mx1 = -1e30f;
#pragma unroll
        for (int j = 0; j < 8; j++) {
            mx0 = fmaxf(mx0, fmaxf(s_[j][0], s_[j][1]));
            mx1 = fmaxf(mx1, fmaxf(s_[j][2], s_[j][3]));
        }
        mx0 = fmaxf(mx0, __shfl_xor_sync(0xffffffffu, mx0, 1));
        mx0 = fmaxf(mx0, __shfl_xor_sync(0xffffffffu, mx0, 2));
        mx1 = fmaxf(mx1, __shfl_xor_sync(0xffffffffu, mx1, 1));
        mx1 = fmaxf(mx1, __shfl_xor_sync(0xffffffffu, mx1, 2));
        const float m0n = fmaxf(m0, mx0), m1n = fmaxf(m1, mx1);
        const float cr0 = __expf(m0 - m0n), cr1 = __expf(m1 - m1n);
        float sum0 = 0.f, sum1 = 0.f;
#pragma unroll
        for (int j = 0; j < 8; j++) {
            s_[j][0] = __expf(s_[j][0] - m0n); sum0 += s_[j][0];
            s_[j][1] = __expf(s_[j][1] - m0n); sum0 += s_[j][1];
            s_[j][2] = __expf(s_[j][2] - m1n); sum1 += s_[j][2];
            s_[j][3] = __expf(s_[j][3] - m1n); sum1 += s_[j][3];
        }
        sum0 += __shfl_xor_sync(0xffffffffu, sum0, 1);
        sum0 += __shfl_xor_sync(0xffffffffu, sum0, 2);
        sum1 += __shfl_xor_sync(0xffffffffu, sum1, 1);
        sum1 += __shfl_xor_sync(0xffffffffu, sum1, 2);
        l0 = l0 * cr0 + sum0;  m0 = m0n;
        l1 = l1 * cr1 + sum1;  m1 = m1n;
#pragma unroll
        for (int v = 0; v < 16; v++) {
            oacc[v][0] *= cr0; oacc[v][1] *= cr0;
            oacc[v][2] *= cr1; oacc[v][3] *= cr1;
        }

        // ---- pack P into A-fragments (hi/lo) ----
        uint32_t ph01[8], ph23[8], pl01[8], pl23[8];
#pragma unroll
        for (int j = 0; j < 8; j++) {
            __nv_bfloat162 h01 = __floats2bfloat162_rn(s_[j][0], s_[j][1]);
            __nv_bfloat162 h23 = __floats2bfloat162_rn(s_[j][2], s_[j][3]);
            ph01[j] = *(uint32_t*)&h01;
            ph23[j] = *(uint32_t*)&h23;
            __nv_bfloat162 lo01 = __floats2bfloat162_rn(
                s_[j][0] - __bfloat162float(h01.x),
                s_[j][1] - __bfloat162float(h01.y));
            __nv_bfloat162 lo23 = __floats2bfloat162_rn(
                s_[j][2] - __bfloat162float(h23.x),
                s_[j][3] - __bfloat162float(h23.y));
            pl01[j] = *(uint32_t*)&lo01;
            pl23[j] = *(uint32_t*)&lo23;
        }

        // ---- O += P V (bf16x3); V via ldmatrix.trans ----
        const uint32_t vaddr = kb + 2 * ATILE + lane * KROW;
#pragma unroll
        for (int t32 = 0; t32 < 2; t32++) {
            uint32_t Ah0[4] = {ph01[4*t32],   ph23[4*t32],   ph01[4*t32+1], ph23[4*t32+1]};
            uint32_t Ah1[4] = {ph01[4*t32+2], ph23[4*t32+2], ph01[4*t32+3], ph23[4*t32+3]};
            uint32_t Al0[4] = {pl01[4*t32],   pl23[4*t32],   pl01[4*t32+1], pl23[4*t32+1]};
            uint32_t Al1[4] = {pl01[4*t32+2], pl23[4*t32+2], pl01[4*t32+3], pl23[4*t32+3]};
#pragma unroll
            for (int v = 0; v < 16; v++) {
                uint32_t vfh[4], vfl[4];
                ldmx4t(vaddr + t32 * 32 * KROW + v * 16, vfh);
                ldmx4t(vaddr + ATILE + t32 * 32 * KROW + v * 16, vfl);
                uint32_t bh0[2] = {vfh[0], vfh[1]}, bh1[2] = {vfh[2], vfh[3]};
                uint32_t bl0[2] = {vfl[0], vfl[1]}, bl1[2] = {vfl[2], vfl[3]};
                mma16816(oacc[v], Ah0, bh0);
                mma16816(oacc[v], Ah1, bh1);
                mma16816(oacc[v], Ah0, bl0);
                mma16816(oacc[v], Ah1, bl1);
                mma16816(oacc[v], Al0, bh0);
                mma16816(oacc[v], Al1, bh1);
            }
        }
        __syncthreads();   // done reading this buffer before next prefetch wave
    }

    // ---- epilogue ----
    const float inv0 = 1.0f / l0, inv1 = 1.0f / l1;
    const size_t r0off = ((size_t)(b * LL + q0 + w * 16 + g)) * (HQ * DD) + h * DD + colq;
    const size_t r1off = r0off + 8 * (size_t)(HQ * DD);
#pragma unroll
    for (int v = 0; v < 16; v++) {
        float2 o0 = make_float2(oacc[v][0] * inv0, oacc[v][1] * inv0);
        float2 o1 = make_float2(oacc[v][2] * inv1, oacc[v][3] * inv1);
        *(float2*)&o_out[r0off + 8 * v] = o0;
        *(float2*)&o_out[r1off + 8 * v] = o1;
    }
}

// ---------------------------------------------------------------------------
// Launch
// ---------------------------------------------------------------------------
extern "C" void kernel_launch(void* const* d_in, const int* in_sizes, int n_in,
                              void* d_out, int out_size)
{
    const float* X  = (const float*)d_in[0];
    const float* Wq = (const float*)d_in[1];
    const float* bq = (const float*)d_in[2];
    const float* Wk = (const float*)d_in[3];
    const float* bk = (const float*)d_in[4];
    const float* Wv = (const float*)d_in[5];
    const float* bv = (const float*)d_in[6];
    const float* Wo = (const float*)d_in[7];
    float* out = (float*)d_out;

    float *qp, *kp, *vp, *ap;
    __nv_bfloat16 *ah, *al, *kh2, *kl2, *vh2, *vl2;
    __nv_bfloat16 *wqh, *wql, *wkh, *wkl, *wvh, *wvl, *woh, *wol;
    cudaGetSymbolAddress((void**)&qp, g_q);
    cudaGetSymbolAddress((void**)&kp, g_k);
    cudaGetSymbolAddress((void**)&vp, g_v);
    cudaGetSymbolAddress((void**)&ap, g_attn);
    cudaGetSymbolAddress((void**)&ah, g_ah);
    cudaGetSymbolAddress((void**)&al, g_al);
    cudaGetSymbolAddress((void**)&kh2, g_kh2);
    cudaGetSymbolAddress((void**)&kl2, g_kl2);
    cudaGetSymbolAddress((void**)&vh2, g_vh2);
    cudaGetSymbolAddress((void**)&vl2, g_vl2);
    cudaGetSymbolAddress((void**)&wqh, g_wqh);
    cudaGetSymbolAddress((void**)&wql, g_wql);
    cudaGetSymbolAddress((void**)&wkh, g_wkh);
    cudaGetSymbolAddress((void**)&wkl, g_wkl);
    cudaGetSymbolAddress((void**)&wvh, g_wvh);
    cudaGetSymbolAddress((void**)&wvl, g_wvl);
    cudaGetSymbolAddress((void**)&woh, g_woh);
    cudaGetSymbolAddress((void**)&wol, g_wol);

    cudaFuncSetAttribute(gemm_bf16x3,
                         cudaFuncAttributeMaxDynamicSharedMemorySize, GSMEM_BYTES);
    cudaFuncSetAttribute(attn_mma,
                         cudaFuncAttributeMaxDynamicSharedMemorySize, ASMEM);

    const int n4x = (int)((size_t)MROWS * EE / 4);
    const int n4kv = (int)((size_t)MROWS * HKV * DD / 4);
    const float scale = 0.08838834764831845f;   // 1/sqrt(128)

    // Split X + transpose/split weights
    split_kernel<<<(n4x + 255) / 256, 256>>>(X, ah, al, n4x);
    tsplit_kernel<<<dim3((HQ*DD)/32, EE/32), dim3(32, 8)>>>(Wq, wqh, wql, EE, HQ*DD);
    tsplit_kernel<<<dim3((HKV*DD)/32, EE/32), dim3(32, 8)>>>(Wk, wkh, wkl, EE, HKV*DD);
    tsplit_kernel<<<dim3((HKV*DD)/32, EE/32), dim3(32, 8)>>>(Wv, wvh, wvl, EE, HKV*DD);
    tsplit_kernel<<<dim3(EE/32, (HQ*DD)/32), dim3(32, 8)>>>(Wo, woh, wol, HQ*DD, EE);

    // QKV projections
    gemm_bf16x3<<<dim3((HQ*DD)/128, MROWS/128), 256, GSMEM_BYTES>>>(
        ah, al, wqh, wql, bq, qp, MROWS, HQ*DD, EE);
    gemm_bf16x3<<<dim3((HKV*DD)/128, MROWS/128), 256, GSMEM_BYTES>>>(
        ah, al, wkh, wkl, bk, kp, MROWS, HKV*DD, EE);
    gemm_bf16x3<<<dim3((HKV*DD)/128, MROWS/128), 256, GSMEM_BYTES>>>(
        ah, al, wvh, wvl, bv, vp, MROWS, HKV*DD, EE);

    // RoPE (scale folded into Q)
    rope_kernel<<<MROWS, 256>>>(qp, HQ, scale);
    rope_kernel<<<MROWS, 256>>>(kp, HKV, 1.0f);

    // Split Q/K/V to bf16 hi/lo (Q reuses X split buffers — gemms done)
    split_kernel<<<(n4x + 255) / 256, 256>>>(qp, ah, al, n4x);
    split_kernel<<<(n4kv + 255) / 256, 256>>>(kp, kh2, kl2, n4kv);
    split_kernel<<<(n4kv + 255) / 256, 256>>>(vp, vh2, vl2, n4kv);

    // Attention on tensor cores
    attn_mma<<<dim3(LL / 128, BB * HQ), 256, ASMEM>>>(ah, al, kh2, kl2, vh2, vl2, ap);

    // Output projection
    split_kernel<<<(n4x + 255) / 256, 256>>>(ap, ah, al, n4x);
    gemm_bf16x3<<<dim3(EE/128, MROWS/128), 256, GSMEM_BYTES>>>(
        ah, al, woh, wol, nullptr, out, MROWS, EE, EE);
}

// round 11
// speedup vs baseline: 1.7974x; 1.0884x over previous
#include <cuda_runtime.h>
#include <cuda_bf16.h>
#include <cstdint>
#include <cstddef>

// Problem constants
#define BB 2
#define LL 2048
#define EE 2048
#define HQ 16
#define HKV 2
#define DD 128
#define MROWS (BB*LL)   // 4096

// ---------------------------------------------------------------------------
// Scratch (device globals — no allocations allowed)
// ---------------------------------------------------------------------------
__device__ float g_q[(size_t)MROWS * HQ * DD];     // 32 MB (Q fp32 pre-rope)
__device__ float g_k[(size_t)MROWS * HKV * DD];    // 4 MB  (K fp32 pre-rope)

// bf16 split activations (X for gemms; then Q hi/lo after rope_split)
__device__ __nv_bfloat16 g_ah[(size_t)MROWS * EE];
__device__ __nv_bfloat16 g_al[(size_t)MROWS * EE];
// bf16 split K / V (post-rope K)
__device__ __nv_bfloat16 g_kh2[(size_t)MROWS * HKV * DD];
__device__ __nv_bfloat16 g_kl2[(size_t)MROWS * HKV * DD];
__device__ __nv_bfloat16 g_vh2[(size_t)MROWS * HKV * DD];
__device__ __nv_bfloat16 g_vl2[(size_t)MROWS * HKV * DD];
// bf16 split attention output
__device__ __nv_bfloat16 g_oh[(size_t)MROWS * HQ * DD];
__device__ __nv_bfloat16 g_ol[(size_t)MROWS * HQ * DD];
// bf16 split transposed weights [N, K] (K-major)
__device__ __nv_bfloat16 g_wqh[(size_t)(HQ*DD) * EE];
__device__ __nv_bfloat16 g_wql[(size_t)(HQ*DD) * EE];
__device__ __nv_bfloat16 g_wkh[(size_t)(HKV*DD) * EE];
__device__ __nv_bfloat16 g_wkl[(size_t)(HKV*DD) * EE];
__device__ __nv_bfloat16 g_wvh[(size_t)(HKV*DD) * EE];
__device__ __nv_bfloat16 g_wvl[(size_t)(HKV*DD) * EE];
__device__ __nv_bfloat16 g_woh[(size_t)EE * (HQ*DD)];
__device__ __nv_bfloat16 g_wol[(size_t)EE * (HQ*DD)];

// ---------------------------------------------------------------------------
// PTX helpers (base-ISA: cp.async / ldmatrix / mma.sync)
// ---------------------------------------------------------------------------
__device__ __forceinline__ uint32_t smem_u32(const void* p) {
    uint32_t a;
    asm("{ .reg .u64 t; cvta.to.shared.u64 t, %1; cvt.u32.u64 %0, t; }"
        : "=r"(a) : "l"(p));
    return a;
}

__device__ __forceinline__ void cpa16(uint32_t d, const void* s) {
    asm volatile("cp.async.cg.shared.global [%0], [%1], 16;" :: "r"(d), "l"(s));
}
#define CP_COMMIT() asm volatile("cp.async.commit_group;")
#define CP_WAIT(n)  asm volatile("cp.async.wait_group %0;" :: "n"(n))

__device__ __forceinline__ void ldmx4(uint32_t a, uint32_t r[4]) {
    asm volatile("ldmatrix.sync.aligned.m8n8.x4.shared.b16 {%0,%1,%2,%3}, [%4];"
                 : "=r"(r[0]), "=r"(r[1]), "=r"(r[2]), "=r"(r[3]) : "r"(a));
}
__device__ __forceinline__ void ldmx2(uint32_t a, uint32_t r[2]) {
    asm volatile("ldmatrix.sync.aligned.m8n8.x2.shared.b16 {%0,%1}, [%2];"
                 : "=r"(r[0]), "=r"(r[1]) : "r"(a));
}
__device__ __forceinline__ void ldmx4t(uint32_t a, uint32_t r[4]) {
    asm volatile("ldmatrix.sync.aligned.m8n8.x4.trans.shared.b16 {%0,%1,%2,%3}, [%4];"
                 : "=r"(r[0]), "=r"(r[1]), "=r"(r[2]), "=r"(r[3]) : "r"(a));
}

__device__ __forceinline__ void mma16816(float c[4], const uint32_t a[4],
                                         const uint32_t b[2]) {
    asm volatile(
        "mma.sync.aligned.m16n8k16.row.col.f32.bf16.bf16.f32 "
        "{%0,%1,%2,%3}, {%4,%5,%6,%7}, {%8,%9}, {%0,%1,%2,%3};"
        : "+f"(c[0]), "+f"(c[1]), "+f"(c[2]), "+f"(c[3])
        : "r"(a[0]), "r"(a[1]), "r"(a[2]), "r"(a[3]), "r"(b[0]), "r"(b[1]));
}

// ---------------------------------------------------------------------------
// split: fp32 -> bf16 hi + bf16 lo
// ---------------------------------------------------------------------------
__global__ void split_kernel(const float* __restrict__ x,
                             __nv_bfloat16* __restrict__ h,
                             __nv_bfloat16* __restrict__ l, int n4)
{
    int i = blockIdx.x * blockDim.x + threadIdx.x;
    if (i >= n4) return;
    float4 v = ((const float4*)x)[i];
    __nv_bfloat16 h0 = __float2bfloat16(v.x);
    __nv_bfloat16 h1 = __float2bfloat16(v.y);
    __nv_bfloat16 h2 = __float2bfloat16(v.z);
    __nv_bfloat16 h3 = __float2bfloat16(v.w);
    __nv_bfloat16 l0 = __float2bfloat16(v.x - __bfloat162float(h0));
    __nv_bfloat16 l1 = __float2bfloat16(v.y - __bfloat162float(h1));
    __nv_bfloat16 l2 = __float2bfloat16(v.z - __bfloat162float(h2));
    __nv_bfloat16 l3 = __float2bfloat16(v.w - __bfloat162float(h3));
    ((__nv_bfloat162*)h)[2*i]   = __halves2bfloat162(h0, h1);
    ((__nv_bfloat162*)h)[2*i+1] = __halves2bfloat162(h2, h3);
    ((__nv_bfloat162*)l)[2*i]   = __halves2bfloat162(l0, l1);
    ((__nv_bfloat162*)l)[2*i+1] = __halves2bfloat162(l2, l3);
}

// ---------------------------------------------------------------------------
// transpose+split: W[K,N] fp32 -> Th,Tl [N,K] bf16
// ---------------------------------------------------------------------------
__global__ void tsplit_kernel(const float* __restrict__ W,
                              __nv_bfloat16* __restrict__ Th,
                              __nv_bfloat16* __restrict__ Tl, int K, int N)
{
    __shared__ float ts[32][33];
    const int n0 = blockIdx.x * 32, k0 = blockIdx.y * 32;
    const int tx = threadIdx.x, ty = threadIdx.y;
    for (int i = ty; i < 32; i += 8)
        ts[i][tx] = W[(size_t)(k0 + i) * N + n0 + tx];
    __syncthreads();
    for (int i = ty; i < 32; i += 8) {
        float v = ts[tx][i];
        __nv_bfloat16 hv = __float2bfloat16(v);
        __nv_bfloat16 lv = __float2bfloat16(v - __bfloat162float(hv));
        size_t o = (size_t)(n0 + i) * K + k0 + tx;
        Th[o] = hv;
        Tl[o] = lv;
    }
}

// ---------------------------------------------------------------------------
// bf16x3 GEMM via mma.sync. 2 CTAs/SM forced.
// ---------------------------------------------------------------------------
#define BKG 32
#define SROW 80
#define TBYTES (128 * SROW)
#define BUFBYTES (4 * TBYTES)
#define GSMEM_BYTES (2 * BUFBYTES)

__device__ __forceinline__ void tile_cp(uint32_t sdst,
                                        const __nv_bfloat16* __restrict__ g,
                                        int ldk, int row0, int k0, int t)
{
    const char* gb = (const char*)(g + (size_t)row0 * ldk + k0);
    const size_t rs = (size_t)ldk * 2;
#pragma unroll
    for (int i = 0; i < 2; i++) {
        int idx = t + i * 256;
        int r = idx >> 2;
        int c = (idx & 3) << 4;
        cpa16(sdst + r * SROW + c, gb + (size_t)r * rs + c);
    }
}

// Shared mainloop: accumulates 128x128 C tile (4x4 fragments per warp)
__device__ __forceinline__ void gemm_core(
    const __nv_bfloat16* __restrict__ Ah, const __nv_bfloat16* __restrict__ Al,
    const __nv_bfloat16* __restrict__ Bh, const __nv_bfloat16* __restrict__ Bl,
    uint32_t sbase, int t, int bm, int bn, int K, float acc[4][4][4])
{
    const int lane = t & 31, wid = t >> 5;
    const int wm = wid & 1, wn = wid >> 1;
    const int NT = K / BKG;

    {
        tile_cp(sbase,              Ah, K, bm, 0, t);
        tile_cp(sbase + TBYTES,     Al, K, bm, 0, t);
        tile_cp(sbase + 2 * TBYTES, Bh, K, bn, 0, t);
        tile_cp(sbase + 3 * TBYTES, Bl, K, bn, 0, t);
        CP_COMMIT();
    }

    const int q = lane >> 3, r8 = lane & 7;
    const int arow = wm * 64 + (q & 1) * 8 + r8;
    const int acolb = ((q >> 1) * 8) * 2;
    const int t16 = lane & 15;
    const int brow = wn * 32 + (t16 & 7);
    const int bcolb = ((t16 >> 3) * 8) * 2;

    for (int kt = 0; kt < NT; kt++) {
        const uint32_t sb = sbase + (kt & 1) * BUFBYTES;
        if (kt + 1 < NT) {
            const uint32_t sn = sbase + ((kt + 1) & 1) * BUFBYTES;
            const int k0 = (kt + 1) * BKG;
            tile_cp(sn,              Ah, K, bm, k0, t);
            tile_cp(sn + TBYTES,     Al, K, bm, k0, t);
            tile_cp(sn + 2 * TBYTES, Bh, K, bn, k0, t);
            tile_cp(sn + 3 * TBYTES, Bl, K, bn, k0, t);
            CP_COMMIT();
            CP_WAIT(1);
        } else {
            CP_WAIT(0);
        }
        __syncthreads();

#pragma unroll
        for (int kk = 0; kk < 2; kk++) {
            const uint32_t abase = sb + arow * SROW + kk * 32 + acolb;
            const uint32_t bbase = sb + 2 * TBYTES + brow * SROW + kk * 32 + bcolb;
            uint32_t ah_[4][4], al_[4][4], bh_[4][2], bl_[4][2];
#pragma unroll
            for (int mt = 0; mt < 4; mt++) {
                ldmx4(abase + mt * 16 * SROW, ah_[mt]);
                ldmx4(abase + TBYTES + mt * 16 * SROW, al_[mt]);
            }
#pragma unroll
            for (int nt = 0; nt < 4; nt++) {
                ldmx2(bbase + nt * 8 * SROW, bh_[nt]);
                ldmx2(bbase + TBYTES + nt * 8 * SROW, bl_[nt]);
            }
#pragma unroll
            for (int mt = 0; mt < 4; mt++)
#pragma unroll
                for (int nt = 0; nt < 4; nt++) {
                    mma16816(acc[mt][nt], ah_[mt], bh_[nt]);
                    mma16816(acc[mt][nt], ah_[mt], bl_[nt]);
                    mma16816(acc[mt][nt], al_[mt], bh_[nt]);
                }
        }
        __syncthreads();
    }
}

__global__ __launch_bounds__(256, 2)
void gemm_bf16x3(const __nv_bfloat16* __restrict__ Ah,
                 const __nv_bfloat16* __restrict__ Al,
                 const __nv_bfloat16* __restrict__ Bh,
                 const __nv_bfloat16* __restrict__ Bl,
                 const float* __restrict__ bias,
                 float* __restrict__ C, int M, int N, int K)
{
    extern __shared__ char sm[];
    const uint32_t sbase = smem_u32(sm);
    const int t = threadIdx.x;
    const int wid = t >> 5, lane = t & 31;
    const int wm = wid & 1, wn = wid >> 1;
    const int bm = blockIdx.y * 128, bn = blockIdx.x * 128;

    float acc[4][4][4];
#pragma unroll
    for (int mt = 0; mt < 4; mt++)
#pragma unroll
        for (int nt = 0; nt < 4; nt++)
#pragma unroll
            for (int i = 0; i < 4; i++) acc[mt][nt][i] = 0.f;

    gemm_core(Ah, Al, Bh, Bl, sbase, t, bm, bn, K, acc);

    const int gid = lane >> 2, tid2 = (lane & 3) * 2;
#pragma unroll
    for (int mt = 0; mt < 4; mt++) {
        const int row = bm + wm * 64 + mt * 16 + gid;
#pragma unroll
        for (int nt = 0; nt < 4; nt++) {
            const int col = bn + wn * 32 + nt * 8 + tid2;
            float b0 = 0.f, b1 = 0.f;
            if (bias) { b0 = bias[col]; b1 = bias[col + 1]; }
            float2 v0 = make_float2(acc[mt][nt][0] + b0, acc[mt][nt][1] + b1);
            float2 v1 = make_float2(acc[mt][nt][2] + b0, acc[mt][nt][3] + b1);
            *(float2*)&C[(size_t)row * N + col] = v0;
            *(float2*)&C[(size_t)(row + 8) * N + col] = v1;
        }
    }
}

// Fused K+V projection: blockIdx.z = 0 -> K (fp32 out, pre-rope),
//                       blockIdx.z = 1 -> V (split bf16 out, final)
__global__ __launch_bounds__(256, 2)
void gemm_kv(const __nv_bfloat16* __restrict__ Ah,
             const __nv_bfloat16* __restrict__ Al,
             const __nv_bfloat16* __restrict__ BhK,
             const __nv_bfloat16* __restrict__ BlK,
             const float* __restrict__ biasK, float* __restrict__ CK,
             const __nv_bfloat16* __restrict__ BhV,
             const __nv_bfloat16* __restrict__ BlV,
             const float* __restrict__ biasV,
             __nv_bfloat16* __restrict__ VH, __nv_bfloat16* __restrict__ VL,
             int M, int N, int K)
{
    extern __shared__ char sm[];
    const uint32_t sbase = smem_u32(sm);
    const int t = threadIdx.x;
    const int wid = t >> 5, lane = t & 31;
    const int wm = wid & 1, wn = wid >> 1;
    const int bm = blockIdx.y * 128, bn = blockIdx.x * 128;
    const int z = blockIdx.z;

    const __nv_bfloat16* Bh = z ? BhV : BhK;
    const __nv_bfloat16* Bl = z ? BlV : BlK;
    const float* bias = z ? biasV : biasK;

    float acc[4][4][4];
#pragma unroll
    for (int mt = 0; mt < 4; mt++)
#pragma unroll
        for (int nt = 0; nt < 4; nt++)
#pragma unroll
            for (int i = 0; i < 4; i++) acc[mt][nt][i] = 0.f;

    gemm_core(Ah, Al, Bh, Bl, sbase, t, bm, bn, K, acc);

    const int gid = lane >> 2, tid2 = (lane & 3) * 2;
#pragma unroll
    for (int mt = 0; mt < 4; mt++) {
        const int row = bm + wm * 64 + mt * 16 + gid;
#pragma unroll
        for (int nt = 0; nt < 4; nt++) {
            const int col = bn + wn * 32 + nt * 8 + tid2;
            const float b0 = bias[col], b1 = bias[col + 1];
            float v0 = acc[mt][nt][0] + b0, v1 = acc[mt][nt][1] + b1;
            float v2 = acc[mt][nt][2] + b0, v3 = acc[mt][nt][3] + b1;
            if (z == 0) {
                *(float2*)&CK[(size_t)row * N + col] = make_float2(v0, v1);
                *(float2*)&CK[(size_t)(row + 8) * N + col] = make_float2(v2, v3);
            } else {
                __nv_bfloat162 h0 = __floats2bfloat162_rn(v0, v1);
                __nv_bfloat162 l0 = __floats2bfloat162_rn(
                    v0 - __bfloat162float(h0.x), v1 - __bfloat162float(h0.y));
                __nv_bfloat162 h1 = __floats2bfloat162_rn(v2, v3);
                __nv_bfloat162 l1 = __floats2bfloat162_rn(
                    v2 - __bfloat162float(h1.x), v3 - __bfloat162float(h1.y));
                *(__nv_bfloat162*)&VH[(size_t)row * N + col] = h0;
                *(__nv_bfloat162*)&VL[(size_t)row * N + col] = l0;
                *(__nv_bfloat162*)&VH[(size_t)(row + 8) * N + col] = h1;
                *(__nv_bfloat162*)&VL[(size_t)(row + 8) * N + col] = l1;
            }
        }
    }
}

// ---------------------------------------------------------------------------
// RoPE + bf16 hi/lo split: x fp32 [B*L, H*D] -> xh, xl bf16
// ---------------------------------------------------------------------------
__global__ void rope_split(const float* __restrict__ x,
                           __nv_bfloat16* __restrict__ xh,
                           __nv_bfloat16* __restrict__ xl,
                           int H, float oscale)
{
    __shared__ float cs[64], sn[64];
    const int row = blockIdx.x;
    const int pos = row & (LL - 1);
    const int t = threadIdx.x;
    if (t < 64) {
        float e   = (float)(2 * t) * (1.0f / (float)DD);
        float inv = powf(1000000.0f, -e);
        float ang = (float)pos * inv;
        cs[t] = cosf(ang);
        sn[t] = sinf(ang);
    }
    __syncthreads();
    const float* xr = x + (size_t)row * H * DD;
    const size_t ob = (size_t)row * H * DD;
    for (int i = t; i < H * 64; i += blockDim.x) {
        int h = i >> 6;
        int d = i & 63;
        float x1 = xr[h * DD + d];
        float x2 = xr[h * DD + d + 64];
        float c = cs[d], s = sn[d];
        float y1 = (x1 * c - x2 * s) * oscale;
        float y2 = (x2 * c + x1 * s) * oscale;
        __nv_bfloat16 h1 = __float2bfloat16(y1);
        __nv_bfloat16 h2 = __float2bfloat16(y2);
        xh[ob + h * DD + d]      = h1;
        xh[ob + h * DD + d + 64] = h2;
        xl[ob + h * DD + d]      = __float2bfloat16(y1 - __bfloat162float(h1));
        xl[ob + h * DD + d + 64] = __float2bfloat16(y2 - __bfloat162float(h2));
    }
}

// ---------------------------------------------------------------------------
// Flash attention on tensor cores (mma.sync bf16x3), causal, GQA G=8.
// CTA = 128 q-rows x one (b,h). Output written as split bf16 directly.
// ---------------------------------------------------------------------------
#define KROW 272                  // 128 bf16 = 256B + 16B pad
#define ATILE (64 * KROW)         // 17408
#define ABUF  (4 * ATILE)         // Kh,Kl,Vh,Vl = 69632
#define ASMEM (2 * ABUF)          // 139264

__global__ __launch_bounds__(256)
void attn_mma(const __nv_bfloat16* __restrict__ Qh,
              const __nv_bfloat16* __restrict__ Ql,
              const __nv_bfloat16* __restrict__ Kh,
              const __nv_bfloat16* __restrict__ Kl,
              const __nv_bfloat16* __restrict__ Vh,
              const __nv_bfloat16* __restrict__ Vl,
              __nv_bfloat16* __restrict__ Oh,
              __nv_bfloat16* __restrict__ Ol)
{
    extern __shared__ char sm[];
    const uint32_t sb = smem_u32(sm);
    const int t = threadIdx.x, w = t >> 5, lane = t & 31;
    const int qt = gridDim.x - 1 - blockIdx.x;   // heavy tiles first
    const int bh = blockIdx.y;
    const int b = bh >> 4, h = bh & 15, hk = h >> 3;
    const int q0 = qt * 128;

    // ---- Load Q tile (hi at sb, lo at sb + 128*KROW) via cp.async ----
    {
        const char* gqh = (const char*)(Qh + ((size_t)(b * LL + q0)) * (HQ * DD) + h * DD);
        const char* gql = (const char*)(Ql + ((size_t)(b * LL + q0)) * (HQ * DD) + h * DD);
#pragma unroll
        for (int i = 0; i < 8; i++) {
            int idx = t + i * 256;
            int r = idx >> 4;
            int c = (idx & 15) << 4;
            cpa16(sb + r * KROW + c,               gqh + (size_t)r * 4096 + c);
            cpa16(sb + 128 * KROW + r * KROW + c,  gql + (size_t)r * 4096 + c);
        }
        CP_COMMIT();
        CP_WAIT(0);
        __syncthreads();
    }

    // ---- ldmatrix Q fragments into registers ----
    uint32_t qfh[8][4], qfl[8][4];
    {
        const int qq = lane >> 3, r8 = lane & 7;
        const uint32_t qaddr = sb + (w * 16 + (qq & 1) * 8 + r8) * KROW + (qq >> 1) * 16;
#pragma unroll
        for (int c = 0; c < 8; c++) {
            ldmx4(qaddr + c * 32, qfh[c]);
            ldmx4(qaddr + 128 * KROW + c * 32, qfl[c]);
        }
    }
    __syncthreads();

    float oacc[16][4];
#pragma unroll
    for (int v = 0; v < 16; v++)
#pragma unroll
        for (int e = 0; e < 4; e++) oacc[v][e] = 0.f;
    float m0 = -1e30f, m1 = -1e30f, l0 = 0.f, l1 = 0.f;

    const int NT = 2 * qt + 2;
    const size_t kvrow = (size_t)(HKV * DD) * 2;

    {
        const size_t roff = ((size_t)(b * LL)) * (HKV * DD) + hk * DD;
        const char* srcs[4] = {(const char*)(Kh + roff), (const char*)(Kl + roff),
                               (const char*)(Vh + roff), (const char*)(Vl + roff)};
#pragma unroll
        for (int i = 0; i < 16; i++) {
            int idx = t + i * 256;
            int mat = idx >> 10;
            int r = (idx >> 4) & 63;
            int c = (idx & 15) << 4;
            cpa16(sb + mat * ATILE + r * KROW + c, srcs[mat] + (size_t)r * kvrow + c);
        }
        CP_COMMIT();
    }

    const int g = lane >> 2;
    const int row0 = q0 + w * 16 + g;
    const int colq = (lane & 3) * 2;

    for (int kt = 0; kt < NT; kt++) {
        if (kt + 1 < NT) {
            const uint32_t nb = sb + ((kt + 1) & 1) * ABUF;
            const size_t roff = ((size_t)(b * LL + (kt + 1) * 64)) * (HKV * DD) + hk * DD;
            const char* srcs[4] = {(const char*)(Kh + roff), (const char*)(Kl + roff),
                                   (const char*)(Vh + roff), (const char*)(Vl + roff)};
#pragma unroll
            for (int i = 0; i < 16; i++) {
                int idx = t + i * 256;
                int mat = idx >> 10;
                int r = (idx >> 4) & 63;
                int c = (idx & 15) << 4;
                cpa16(nb + mat * ATILE + r * KROW + c, srcs[mat] + (size_t)r * kvrow + c);
            }
            CP_COMMIT();
            CP_WAIT(1);
        } else {
            CP_WAIT(0);
        }
        __syncthreads();

        const uint32_t kb = sb + (kt & 1) * ABUF;
        const int kv0 = kt * 64;

        // ---- S = Q K^T (bf16x3) ----
        float s_[8][4];
#pragma unroll
        for (int j = 0; j < 8; j++)
#pragma unroll
            for (int e = 0; e < 4; e++) s_[j][e] = 0.f;

        const uint32_t kaddr = kb + (lane & 7) * KROW + (lane >> 3) * 16;
#pragma unroll
        for (int c32 = 0; c32 < 4; c32++) {
#pragma unroll
            for (int j = 0; j < 8; j++) {
                uint32_t kfh[4], kfl[4];
                ldmx4(kaddr + j * 8 * KROW + c32 * 64, kfh);
                ldmx4(kaddr + ATILE + j * 8 * KROW + c32 * 64, kfl);
                uint32_t bh0[2] = {kfh[0], kfh[1]}, bh1[2] = {kfh[2], kfh[3]};
                uint32_t bl0[2] = {kfl[0], kfl[1]}, bl1[2] = {kfl[2], kfl[3]};
                mma16816(s_[j], qfh[2 * c32],     bh0);
                mma16816(s_[j], qfh[2 * c32 + 1], bh1);
                mma16816(s_[j], qfh[2 * c32],     bl0);
                mma16816(s_[j], qfh[2 * c32 + 1], bl1);
                mma16816(s_[j], qfl[2 * c32],     bh0);
                mma16816(s_[j], qfl[2 * c32 + 1], bh1);
            }
        }

        // ---- causal mask ----
#pragma unroll
        for (int j = 0; j < 8; j++) {
            int c0 = kv0 + 8 * j + colq;
            if (c0 > row0)     s_[j][0] = -1e30f;
            if (c0 + 1 > row0) s_[j][1] = -1e30f;
            if (c0 > row0 + 8)     s_[j][2] = -1e30f;
            if (c0 + 1 > row0 + 8) s_[j][3] = -1e30f;
        }

        // ---- online softmax ----
        float mx0 = -1e30f, mx1 = -1e30f;
#pragma unroll
        for (int j = 0; j < 8; j++) {
            mx0 = fmaxf(mx0, fmaxf(s_[j][0], s_[j][1]));
            mx1 = fmaxf(mx1, fmaxf(s_[j][2], s_[j][3]));
        }
        mx0 = fmaxf(mx0, __shfl_xor_sync(0xffffffffu, mx0, 1));
        mx0 = fmaxf(mx0, __shfl_xor_sync(0xffffffffu, mx0, 2));
        mx1 = fmaxf(mx1, __shfl_xor_sync(0xffffffffu, mx1, 1));
        mx1 = fmaxf(mx1, __shfl_xor_sync(0xffffffffu, mx1, 2));
        const float m0n = fmaxf(m0, mx0), m1n = fmaxf(m1, mx1);
        const float cr0 = __expf(m0 - m0n), cr1 = __expf(m1 - m1n);
        float sum0 = 0.f, sum1 = 0.f;
#pragma unroll
        for (int j = 0; j < 8; j++) {
            s_[j][0] = __expf(s_[j][0] - m0n); sum0 += s_[j][0];
            s_[j][1] = __expf(s_[j][1] - m0n); sum0 += s_[j][1];
            s_[j][2] = __expf(s_[j][2] - m1n); sum1 += s_[j][2];
            s_[j][3] = __expf(s_[j][3] - m1n); sum1 += s_[j][3];
        }
        sum0 += __shfl_xor_sync(0xffffffffu, sum0, 1);
        sum0 += __shfl_xor_sync(0xffffffffu, sum0, 2);
        sum1 += __shfl_xor_sync(0xffffffffu, sum1, 1);
        sum1 += __shfl_xor_sync(0xffffffffu, sum1, 2);
        l0 = l0 * cr0 + sum0;  m0 = m0n;
        l1 = l1 * cr1 + sum1;  m1 = m1n;
#pragma unroll
        for (int v = 0; v < 16; v++) {
            oacc[v][0] *= cr0; oacc[v][1] *= cr0;
            oacc[v][2] *= cr1; oacc[v][3] *= cr1;
        }

        // ---- pack P into A-fragments (hi/lo) ----
        uint32_t ph01[8], ph23[8], pl01[8], pl23[8];
#pragma unroll
        for (int j = 0; j < 8; j++) {
            __nv_bfloat162 h01 = __floats2bfloat162_rn(s_[j][0], s_[j][1]);
            __nv_bfloat162 h23 = __floats2bfloat162_rn(s_[j][2], s_[j][3]);
            ph01[j] = *(uint32_t*)&h01;
            ph23[j] = *(uint32_t*)&h23;
            __nv_bfloat162 lo01 = __floats2bfloat162_rn(
                s_[j][0] - __bfloat162float(h01.x),
                s_[j][1] - __bfloat162float(h01.y));
            __nv_bfloat162 lo23 = __floats2bfloat162_rn(
                s_[j][2] - __bfloat162float(h23.x),
                s_[j][3] - __bfloat162float(h23.y));
            pl01[j] = *(uint32_t*)&lo01;
            pl23[j] = *(uint32_t*)&lo23;
        }

        // ---- O += P V (bf16x3); V via ldmatrix.trans ----
        const uint32_t vaddr = kb + 2 * ATILE + lane * KROW;
#pragma unroll
        for (int t32 = 0; t32 < 2; t32++) {
            uint32_t Ah0[4] = {ph01[4*t32],   ph23[4*t32],   ph01[4*t32+1], ph23[4*t32+1]};
            uint32_t Ah1[4] = {ph01[4*t32+2], ph23[4*t32+2], ph01[4*t32+3], ph23[4*t32+3]};
            uint32_t Al0[4] = {pl01[4*t32],   pl23[4*t32],   pl01[4*t32+1], pl23[4*t32+1]};
            uint32_t Al1[4] = {pl01[4*t32+2], pl23[4*t32+2], pl01[4*t32+3], pl23[4*t32+3]};
#pragma unroll
            for (int v = 0; v < 16; v++) {
                uint32_t vfh[4], vfl[4];
                ldmx4t(vaddr + t32 * 32 * KROW + v * 16, vfh);
                ldmx4t(vaddr + ATILE + t32 * 32 * KROW + v * 16, vfl);
                uint32_t bh0[2] = {vfh[0], vfh[1]}, bh1[2] = {vfh[2], vfh[3]};
                uint32_t bl0[2] = {vfl[0], vfl[1]}, bl1[2] = {vfl[2], vfl[3]};
                mma16816(oacc[v], Ah0, bh0);
                mma16816(oacc[v], Ah1, bh1);
                mma16816(oacc[v], Ah0, bl0);
                mma16816(oacc[v], Ah1, bl1);
                mma16816(oacc[v], Al0, bh0);
                mma16816(oacc[v], Al1, bh1);
            }
        }
        __syncthreads();
    }

    // ---- epilogue: write split bf16 directly ----
    const float inv0 = 1.0f / l0, inv1 = 1.0f / l1;
    const size_t r0off = ((size_t)(b * LL + q0 + w * 16 + g)) * (HQ * DD) + h * DD + colq;
    const size_t r1off = r0off + 8 * (size_t)(HQ * DD);
#pragma unroll
    for (int v = 0; v < 16; v++) {
        float a0 = oacc[v][0] * inv0, a1 = oacc[v][1] * inv0;
        float a2 = oacc[v][2] * inv1, a3 = oacc[v][3] * inv1;
        __nv_bfloat162 h0 = __floats2bfloat162_rn(a0, a1);
        __nv_bfloat162 lo0 = __floats2bfloat162_rn(
            a0 - __bfloat162float(h0.x), a1 - __bfloat162float(h0.y));
        __nv_bfloat162 h1 = __floats2bfloat162_rn(a2, a3);
        __nv_bfloat162 lo1 = __floats2bfloat162_rn(
            a2 - __bfloat162float(h1.x), a3 - __bfloat162float(h1.y));
        *(__nv_bfloat162*)&Oh[r0off + 8 * v] = h0;
        *(__nv_bfloat162*)&Ol[r0off + 8 * v] = lo0;
        *(__nv_bfloat162*)&Oh[r1off + 8 * v] = h1;
        *(__nv_bfloat162*)&Ol[r1off + 8 * v] = lo1;
    }
}

// ---------------------------------------------------------------------------
// Launch
// ---------------------------------------------------------------------------
extern "C" void kernel_launch(void* const* d_in, const int* in_sizes, int n_in,
                              void* d_out, int out_size)
{
    const float* X  = (const float*)d_in[0];
    const float* Wq = (const float*)d_in[1];
    const float* bq = (const float*)d_in[2];
    const float* Wk = (const float*)d_in[3];
    const float* bk = (const float*)d_in[4];
    const float* Wv = (const float*)d_in[5];
    const float* bv = (const float*)d_in[6];
    const float* Wo = (const float*)d_in[7];
    float* out = (float*)d_out;

    float *qp, *kp;
    __nv_bfloat16 *ah, *al, *kh2, *kl2, *vh2, *vl2, *oh, *ol;
    __nv_bfloat16 *wqh, *wql, *wkh, *wkl, *wvh, *wvl, *woh, *wol;
    cudaGetSymbolAddress((void**)&qp, g_q);
    cudaGetSymbolAddress((void**)&kp, g_k);
    cudaGetSymbolAddress((void**)&ah, g_ah);
    cudaGetSymbolAddress((void**)&al, g_al);
    cudaGetSymbolAddress((void**)&kh2, g_kh2);
    cudaGetSymbolAddress((void**)&kl2, g_kl2);
    cudaGetSymbolAddress((void**)&vh2, g_vh2);
    cudaGetSymbolAddress((void**)&vl2, g_vl2);
    cudaGetSymbolAddress((void**)&oh, g_oh);
    cudaGetSymbolAddress((void**)&ol, g_ol);
    cudaGetSymbolAddress((void**)&wqh, g_wqh);
    cudaGetSymbolAddress((void**)&wql, g_wql);
    cudaGetSymbolAddress((void**)&wkh, g_wkh);
    cudaGetSymbolAddress((void**)&wkl, g_wkl);
    cudaGetSymbolAddress((void**)&wvh, g_wvh);
    cudaGetSymbolAddress((void**)&wvl, g_wvl);
    cudaGetSymbolAddress((void**)&woh, g_woh);
    cudaGetSymbolAddress((void**)&wol, g_wol);

    cudaFuncSetAttribute(gemm_bf16x3,
                         cudaFuncAttributeMaxDynamicSharedMemorySize, GSMEM_BYTES);
    cudaFuncSetAttribute(gemm_kv,
                         cudaFuncAttributeMaxDynamicSharedMemorySize, GSMEM_BYTES);
    cudaFuncSetAttribute(attn_mma,
                         cudaFuncAttributeMaxDynamicSharedMemorySize, ASMEM);

    const int n4x = (int)((size_t)MROWS * EE / 4);
    const float scale = 0.08838834764831845f;   // 1/sqrt(128)

    // Split X + transpose/split weights
    split_kernel<<<(n4x + 255) / 256, 256>>>(X, ah, al, n4x);
    tsplit_kernel<<<dim3((HQ*DD)/32, EE/32), dim3(32, 8)>>>(Wq, wqh, wql, EE, HQ*DD);
    tsplit_kernel<<<dim3((HKV*DD)/32, EE/32), dim3(32, 8)>>>(Wk, wkh, wkl, EE, HKV*DD);
    tsplit_kernel<<<dim3((HKV*DD)/32, EE/32), dim3(32, 8)>>>(Wv, wvh, wvl, EE, HKV*DD);
    tsplit_kernel<<<dim3(EE/32, (HQ*DD)/32), dim3(32, 8)>>>(Wo, woh, wol, HQ*DD, EE);

    // Q projection (fp32 out, pre-rope)
    gemm_bf16x3<<<dim3((HQ*DD)/128, MROWS/128), 256, GSMEM_BYTES>>>(
        ah, al, wqh, wql, bq, qp, MROWS, HQ*DD, EE);
    // K + V projections fused (K fp32 pre-rope; V split bf16 final)
    gemm_kv<<<dim3((HKV*DD)/128, MROWS/128, 2), 256, GSMEM_BYTES>>>(
        ah, al, wkh, wkl, bk, kp, wvh, wvl, bv, vh2, vl2, MROWS, HKV*DD, EE);

    // RoPE + split (Q scaled by 1/sqrt(D)); Q overwrites X split buffers
    rope_split<<<MROWS, 256>>>(qp, ah, al, HQ, scale);
    rope_split<<<MROWS, 256>>>(kp, kh2, kl2, HKV, 1.0f);

    // Attention on tensor cores -> split bf16 output
    attn_mma<<<dim3(LL / 128, BB * HQ), 256, ASMEM>>>(
        ah, al, kh2, kl2, vh2, vl2, oh, ol);

    // Output projection
    gemm_bf16x3<<<dim3(EE/128, MROWS/128), 256, GSMEM_BYTES>>>(
        oh, ol, woh, wol, nullptr, out, MROWS, EE, EE);
}

// round 12
// speedup vs baseline: 1.8912x; 1.0522x over previous
#include <cuda_runtime.h>
#include <cuda_bf16.h>
#include <cstdint>
#include <cstddef>

// Problem constants
#define BB 2
#define LL 2048
#define EE 2048
#define HQ 16
#define HKV 2
#define DD 128
#define MROWS (BB*LL)   // 4096

// ---------------------------------------------------------------------------
// Scratch (device globals — no allocations allowed)
// ---------------------------------------------------------------------------
__device__ float g_q[(size_t)MROWS * HQ * DD];     // 32 MB (Q fp32 pre-rope)
__device__ float g_k[(size_t)MROWS * HKV * DD];    // 4 MB  (K fp32 pre-rope)

// bf16 split activations (X for gemms; then Q hi/lo after rope_split)
__device__ __nv_bfloat16 g_ah[(size_t)MROWS * EE];
__device__ __nv_bfloat16 g_al[(size_t)MROWS * EE];
// bf16 split K / V (post-rope K)
__device__ __nv_bfloat16 g_kh2[(size_t)MROWS * HKV * DD];
__device__ __nv_bfloat16 g_kl2[(size_t)MROWS * HKV * DD];
__device__ __nv_bfloat16 g_vh2[(size_t)MROWS * HKV * DD];
__device__ __nv_bfloat16 g_vl2[(size_t)MROWS * HKV * DD];
// bf16 split attention output
__device__ __nv_bfloat16 g_oh[(size_t)MROWS * HQ * DD];
__device__ __nv_bfloat16 g_ol[(size_t)MROWS * HQ * DD];
// bf16 split transposed weights [N, K] (K-major)
__device__ __nv_bfloat16 g_wqh[(size_t)(HQ*DD) * EE];
__device__ __nv_bfloat16 g_wql[(size_t)(HQ*DD) * EE];
__device__ __nv_bfloat16 g_wkh[(size_t)(HKV*DD) * EE];
__device__ __nv_bfloat16 g_wkl[(size_t)(HKV*DD) * EE];
__device__ __nv_bfloat16 g_wvh[(size_t)(HKV*DD) * EE];
__device__ __nv_bfloat16 g_wvl[(size_t)(HKV*DD) * EE];
__device__ __nv_bfloat16 g_woh[(size_t)EE * (HQ*DD)];
__device__ __nv_bfloat16 g_wol[(size_t)EE * (HQ*DD)];

// ---------------------------------------------------------------------------
// PTX helpers (base-ISA: cp.async / ldmatrix / mma.sync)
// ---------------------------------------------------------------------------
__device__ __forceinline__ uint32_t smem_u32(const void* p) {
    uint32_t a;
    asm("{ .reg .u64 t; cvta.to.shared.u64 t, %1; cvt.u32.u64 %0, t; }"
        : "=r"(a) : "l"(p));
    return a;
}

__device__ __forceinline__ void cpa16(uint32_t d, const void* s) {
    asm volatile("cp.async.cg.shared.global [%0], [%1], 16;" :: "r"(d), "l"(s));
}
#define CP_COMMIT() asm volatile("cp.async.commit_group;")
#define CP_WAIT(n)  asm volatile("cp.async.wait_group %0;" :: "n"(n))

__device__ __forceinline__ void ldmx4(uint32_t a, uint32_t r[4]) {
    asm volatile("ldmatrix.sync.aligned.m8n8.x4.shared.b16 {%0,%1,%2,%3}, [%4];"
                 : "=r"(r[0]), "=r"(r[1]), "=r"(r[2]), "=r"(r[3]) : "r"(a));
}
__device__ __forceinline__ void ldmx4t(uint32_t a, uint32_t r[4]) {
    asm volatile("ldmatrix.sync.aligned.m8n8.x4.trans.shared.b16 {%0,%1,%2,%3}, [%4];"
                 : "=r"(r[0]), "=r"(r[1]), "=r"(r[2]), "=r"(r[3]) : "r"(a));
}

__device__ __forceinline__ void mma16816(float c[4], const uint32_t a[4],
                                         const uint32_t b[2]) {
    asm volatile(
        "mma.sync.aligned.m16n8k16.row.col.f32.bf16.bf16.f32 "
        "{%0,%1,%2,%3}, {%4,%5,%6,%7}, {%8,%9}, {%0,%1,%2,%3};"
        : "+f"(c[0]), "+f"(c[1]), "+f"(c[2]), "+f"(c[3])
        : "r"(a[0]), "r"(a[1]), "r"(a[2]), "r"(a[3]), "r"(b[0]), "r"(b[1]));
}

// ---------------------------------------------------------------------------
// split: fp32 -> bf16 hi + bf16 lo
// ---------------------------------------------------------------------------
__global__ void split_kernel(const float* __restrict__ x,
                             __nv_bfloat16* __restrict__ h,
                             __nv_bfloat16* __restrict__ l, int n4)
{
    int i = blockIdx.x * blockDim.x + threadIdx.x;
    if (i >= n4) return;
    float4 v = ((const float4*)x)[i];
    __nv_bfloat16 h0 = __float2bfloat16(v.x);
    __nv_bfloat16 h1 = __float2bfloat16(v.y);
    __nv_bfloat16 h2 = __float2bfloat16(v.z);
    __nv_bfloat16 h3 = __float2bfloat16(v.w);
    __nv_bfloat16 l0 = __float2bfloat16(v.x - __bfloat162float(h0));
    __nv_bfloat16 l1 = __float2bfloat16(v.y - __bfloat162float(h1));
    __nv_bfloat16 l2 = __float2bfloat16(v.z - __bfloat162float(h2));
    __nv_bfloat16 l3 = __float2bfloat16(v.w - __bfloat162float(h3));
    ((__nv_bfloat162*)h)[2*i]   = __halves2bfloat162(h0, h1);
    ((__nv_bfloat162*)h)[2*i+1] = __halves2bfloat162(h2, h3);
    ((__nv_bfloat162*)l)[2*i]   = __halves2bfloat162(l0, l1);
    ((__nv_bfloat162*)l)[2*i+1] = __halves2bfloat162(l2, l3);
}

// ---------------------------------------------------------------------------
// fused transpose+split of all 4 weights: W[K,N] fp32 -> Th,Tl [N,K] bf16
// grid (64, 64, 4); out-of-range blocks for small weights exit early
// ---------------------------------------------------------------------------
__global__ void tsplit4_kernel(
    const float* __restrict__ W0, __nv_bfloat16* __restrict__ h0, __nv_bfloat16* __restrict__ l0,
    const float* __restrict__ W1, __nv_bfloat16* __restrict__ h1, __nv_bfloat16* __restrict__ l1,
    const float* __restrict__ W2, __nv_bfloat16* __restrict__ h2, __nv_bfloat16* __restrict__ l2,
    const float* __restrict__ W3, __nv_bfloat16* __restrict__ h3, __nv_bfloat16* __restrict__ l3)
{
    const float* W; __nv_bfloat16 *Th, *Tl; int K, N;
    switch (blockIdx.z) {
        case 0: W = W0; Th = h0; Tl = l0; K = EE;    N = HQ*DD;  break;
        case 1: W = W1; Th = h1; Tl = l1; K = EE;    N = HKV*DD; break;
        case 2: W = W2; Th = h2; Tl = l2; K = EE;    N = HKV*DD; break;
        default:W = W3; Th = h3; Tl = l3; K = HQ*DD; N = EE;     break;
    }
    const int n0 = blockIdx.x * 32, k0 = blockIdx.y * 32;
    if (n0 >= N || k0 >= K) return;

    __shared__ float ts[32][33];
    const int tx = threadIdx.x, ty = threadIdx.y;
    for (int i = ty; i < 32; i += 8)
        ts[i][tx] = W[(size_t)(k0 + i) * N + n0 + tx];
    __syncthreads();
    for (int i = ty; i < 32; i += 8) {
        float v = ts[tx][i];
        __nv_bfloat16 hv = __float2bfloat16(v);
        __nv_bfloat16 lv = __float2bfloat16(v - __bfloat162float(hv));
        size_t o = (size_t)(n0 + i) * K + k0 + tx;
        Th[o] = hv;
        Tl[o] = lv;
    }
}

// ---------------------------------------------------------------------------
// bf16x3 GEMM core via mma.sync. 2 CTAs/SM.
// ---------------------------------------------------------------------------
#define BKG 32
#define SROW 80
#define TBYTES (128 * SROW)
#define BUFBYTES (4 * TBYTES)
#define GSMEM_BYTES (2 * BUFBYTES)

__device__ __forceinline__ void tile_cp(uint32_t sdst,
                                        const __nv_bfloat16* __restrict__ g,
                                        int ldk, int row0, int k0, int t)
{
    const char* gb = (const char*)(g + (size_t)row0 * ldk + k0);
    const size_t rs = (size_t)ldk * 2;
#pragma unroll
    for (int i = 0; i < 2; i++) {
        int idx = t + i * 256;
        int r = idx >> 2;
        int c = (idx & 3) << 4;
        cpa16(sdst + r * SROW + c, gb + (size_t)r * rs + c);
    }
}

__device__ __forceinline__ void gemm_core(
    const __nv_bfloat16* __restrict__ Ah, const __nv_bfloat16* __restrict__ Al,
    const __nv_bfloat16* __restrict__ Bh, const __nv_bfloat16* __restrict__ Bl,
    uint32_t sbase, int t, int bm, int bn, int K, float acc[4][4][4])
{
    const int lane = t & 31, wid = t >> 5;
    const int wm = wid & 1, wn = wid >> 1;
    const int NT = K / BKG;

    {
        tile_cp(sbase,              Ah, K, bm, 0, t);
        tile_cp(sbase + TBYTES,     Al, K, bm, 0, t);
        tile_cp(sbase + 2 * TBYTES, Bh, K, bn, 0, t);
        tile_cp(sbase + 3 * TBYTES, Bl, K, bn, 0, t);
        CP_COMMIT();
    }

    const int q = lane >> 3, r8 = lane & 7;
    const int arow = wm * 64 + (q & 1) * 8 + r8;
    const int acolb = ((q >> 1) * 8) * 2;
    const int t16 = lane & 15;
    // ldmx4 B addressing: lanes 0-15 -> nt even rows, lanes 16-31 -> nt odd (+8 n-rows)
    const int b4row = wn * 32 + (t16 & 7) + ((lane >> 4) * 8);
    const int b4colb = (t16 >> 3) * 16;

    for (int kt = 0; kt < NT; kt++) {
        const uint32_t sb = sbase + (kt & 1) * BUFBYTES;
        if (kt + 1 < NT) {
            const uint32_t sn = sbase + ((kt + 1) & 1) * BUFBYTES;
            const int k0 = (kt + 1) * BKG;
            tile_cp(sn,              Ah, K, bm, k0, t);
            tile_cp(sn + TBYTES,     Al, K, bm, k0, t);
            tile_cp(sn + 2 * TBYTES, Bh, K, bn, k0, t);
            tile_cp(sn + 3 * TBYTES, Bl, K, bn, k0, t);
            CP_COMMIT();
            CP_WAIT(1);
        } else {
            CP_WAIT(0);
        }
        __syncthreads();

#pragma unroll
        for (int kk = 0; kk < 2; kk++) {
            const uint32_t abase = sb + arow * SROW + kk * 32 + acolb;
            const uint32_t bbase = sb + 2 * TBYTES + b4row * SROW + kk * 32 + b4colb;
            uint32_t ah_[4][4], al_[4][4], bh_[4][2], bl_[4][2];
#pragma unroll
            for (int mt = 0; mt < 4; mt++) {
                ldmx4(abase + mt * 16 * SROW, ah_[mt]);
                ldmx4(abase + TBYTES + mt * 16 * SROW, al_[mt]);
            }
#pragma unroll
            for (int ntp = 0; ntp < 2; ntp++) {
                uint32_t r4[4];
                ldmx4(bbase + ntp * 16 * SROW, r4);
                bh_[2*ntp][0] = r4[0]; bh_[2*ntp][1] = r4[1];
                bh_[2*ntp+1][0] = r4[2]; bh_[2*ntp+1][1] = r4[3];
                ldmx4(bbase + TBYTES + ntp * 16 * SROW, r4);
                bl_[2*ntp][0] = r4[0]; bl_[2*ntp][1] = r4[1];
                bl_[2*ntp+1][0] = r4[2]; bl_[2*ntp+1][1] = r4[3];
            }
#pragma unroll
            for (int mt = 0; mt < 4; mt++)
#pragma unroll
                for (int nt = 0; nt < 4; nt++) {
                    mma16816(acc[mt][nt], ah_[mt], bh_[nt]);
                    mma16816(acc[mt][nt], ah_[mt], bl_[nt]);
                    mma16816(acc[mt][nt], al_[mt], bh_[nt]);
                }
        }
        __syncthreads();
    }
}

// Fused QKV projection. 1D grid of 640 CTAs:
//   [0,512)   Q tiles: fp32 out
//   [512,576) K tiles: fp32 out
//   [576,640) V tiles: split bf16 out
__global__ __launch_bounds__(256, 2)
void gemm_qkv(const __nv_bfloat16* __restrict__ Ah,
              const __nv_bfloat16* __restrict__ Al,
              const __nv_bfloat16* __restrict__ BhQ, const __nv_bfloat16* __restrict__ BlQ,
              const float* __restrict__ bQ, float* __restrict__ CQ,
              const __nv_bfloat16* __restrict__ BhK, const __nv_bfloat16* __restrict__ BlK,
              const float* __restrict__ bK, float* __restrict__ CK,
              const __nv_bfloat16* __restrict__ BhV, const __nv_bfloat16* __restrict__ BlV,
              const float* __restrict__ bV,
              __nv_bfloat16* __restrict__ VH, __nv_bfloat16* __restrict__ VL)
{
    extern __shared__ char sm[];
    const uint32_t sbase = smem_u32(sm);
    const int t = threadIdx.x;
    const int wid = t >> 5, lane = t & 31;
    const int wm = wid & 1, wn = wid >> 1;
    const int bid = blockIdx.x;

    const __nv_bfloat16 *Bh, *Bl;
    const float* bias;
    float* Cout = nullptr;
    int bm, bn, N, mode;
    if (bid < 512) {
        Bh = BhQ; Bl = BlQ; bias = bQ; Cout = CQ;
        bn = (bid & 15) * 128; bm = (bid >> 4) * 128;
        N = HQ * DD; mode = 0;
    } else if (bid < 576) {
        int idx = bid - 512;
        Bh = BhK; Bl = BlK; bias = bK; Cout = CK;
        bn = (idx & 1) * 128; bm = (idx >> 1) * 128;
        N = HKV * DD; mode = 0;
    } else {
        int idx = bid - 576;
        Bh = BhV; Bl = BlV; bias = bV;
        bn = (idx & 1) * 128; bm = (idx >> 1) * 128;
        N = HKV * DD; mode = 1;
    }

    float acc[4][4][4];
#pragma unroll
    for (int mt = 0; mt < 4; mt++)
#pragma unroll
        for (int nt = 0; nt < 4; nt++)
#pragma unroll
            for (int i = 0; i < 4; i++) acc[mt][nt][i] = 0.f;

    gemm_core(Ah, Al, Bh, Bl, sbase, t, bm, bn, EE, acc);

    const int gid = lane >> 2, tid2 = (lane & 3) * 2;
#pragma unroll
    for (int mt = 0; mt < 4; mt++) {
        const int row = bm + wm * 64 + mt * 16 + gid;
#pragma unroll
        for (int nt = 0; nt < 4; nt++) {
            const int col = bn + wn * 32 + nt * 8 + tid2;
            const float b0 = bias[col], b1 = bias[col + 1];
            float v0 = acc[mt][nt][0] + b0, v1 = acc[mt][nt][1] + b1;
            float v2 = acc[mt][nt][2] + b0, v3 = acc[mt][nt][3] + b1;
            if (mode == 0) {
                *(float2*)&Cout[(size_t)row * N + col] = make_float2(v0, v1);
                *(float2*)&Cout[(size_t)(row + 8) * N + col] = make_float2(v2, v3);
            } else {
                __nv_bfloat162 h0 = __floats2bfloat162_rn(v0, v1);
                __nv_bfloat162 l0 = __floats2bfloat162_rn(
                    v0 - __bfloat162float(h0.x), v1 - __bfloat162float(h0.y));
                __nv_bfloat162 h1 = __floats2bfloat162_rn(v2, v3);
                __nv_bfloat162 l1 = __floats2bfloat162_rn(
                    v2 - __bfloat162float(h1.x), v3 - __bfloat162float(h1.y));
                *(__nv_bfloat162*)&VH[(size_t)row * N + col] = h0;
                *(__nv_bfloat162*)&VL[(size_t)row * N + col] = l0;
                *(__nv_bfloat162*)&VH[(size_t)(row + 8) * N + col] = h1;
                *(__nv_bfloat162*)&VL[(size_t)(row + 8) * N + col] = l1;
            }
        }
    }
}

// O projection (fp32 out, no bias)
__global__ __launch_bounds__(256, 2)
void gemm_bf16x3(const __nv_bfloat16* __restrict__ Ah,
                 const __nv_bfloat16* __restrict__ Al,
                 const __nv_bfloat16* __restrict__ Bh,
                 const __nv_bfloat16* __restrict__ Bl,
                 float* __restrict__ C, int M, int N, int K)
{
    extern __shared__ char sm[];
    const uint32_t sbase = smem_u32(sm);
    const int t = threadIdx.x;
    const int wid = t >> 5, lane = t & 31;
    const int wm = wid & 1, wn = wid >> 1;
    const int bm = blockIdx.y * 128, bn = blockIdx.x * 128;

    float acc[4][4][4];
#pragma unroll
    for (int mt = 0; mt < 4; mt++)
#pragma unroll
        for (int nt = 0; nt < 4; nt++)
#pragma unroll
            for (int i = 0; i < 4; i++) acc[mt][nt][i] = 0.f;

    gemm_core(Ah, Al, Bh, Bl, sbase, t, bm, bn, K, acc);

    const int gid = lane >> 2, tid2 = (lane & 3) * 2;
#pragma unroll
    for (int mt = 0; mt < 4; mt++) {
        const int row = bm + wm * 64 + mt * 16 + gid;
#pragma unroll
        for (int nt = 0; nt < 4; nt++) {
            const int col = bn + wn * 32 + nt * 8 + tid2;
            *(float2*)&C[(size_t)row * N + col] =
                make_float2(acc[mt][nt][0], acc[mt][nt][1]);
            *(float2*)&C[(size_t)(row + 8) * N + col] =
                make_float2(acc[mt][nt][2], acc[mt][nt][3]);
        }
    }
}

// ---------------------------------------------------------------------------
// fused RoPE + bf16 split for Q and K: grid (MROWS, 2); z=0 Q, z=1 K
// ---------------------------------------------------------------------------
__global__ void rope_split2(const float* __restrict__ q,
                            __nv_bfloat16* __restrict__ qh,
                            __nv_bfloat16* __restrict__ ql,
                            const float* __restrict__ k,
                            __nv_bfloat16* __restrict__ kh,
                            __nv_bfloat16* __restrict__ kl, float qscale)
{
    __shared__ float cs[64], sn[64];
    const int row = blockIdx.x;
    const int z = blockIdx.y;
    const int pos = row & (LL - 1);
    const int t = threadIdx.x;
    if (t < 64) {
        float e   = (float)(2 * t) * (1.0f / (float)DD);
        float inv = powf(1000000.0f, -e);
        float ang = (float)pos * inv;
        cs[t] = cosf(ang);
        sn[t] = sinf(ang);
    }
    __syncthreads();
    const int H = z ? HKV : HQ;
    const float oscale = z ? 1.0f : qscale;
    const float* xr = (z ? k : q) + (size_t)row * H * DD;
    __nv_bfloat16* xh = z ? kh : qh;
    __nv_bfloat16* xl = z ? kl : ql;
    const size_t ob = (size_t)row * H * DD;
    for (int i = t; i < H * 64; i += blockDim.x) {
        int h = i >> 6;
        int d = i & 63;
        float x1 = xr[h * DD + d];
        float x2 = xr[h * DD + d + 64];
        float c = cs[d], s = sn[d];
        float y1 = (x1 * c - x2 * s) * oscale;
        float y2 = (x2 * c + x1 * s) * oscale;
        __nv_bfloat16 h1 = __float2bfloat16(y1);
        __nv_bfloat16 h2 = __float2bfloat16(y2);
        xh[ob + h * DD + d]      = h1;
        xh[ob + h * DD + d + 64] = h2;
        xl[ob + h * DD + d]      = __float2bfloat16(y1 - __bfloat162float(h1));
        xl[ob + h * DD + d + 64] = __float2bfloat16(y2 - __bfloat162float(h2));
    }
}

// ---------------------------------------------------------------------------
// Flash attention on tensor cores (mma.sync bf16x3), causal, GQA G=8.
// ---------------------------------------------------------------------------
#define KROW 272                  // 128 bf16 = 256B + 16B pad
#define ATILE (64 * KROW)         // 17408
#define ABUF  (4 * ATILE)         // Kh,Kl,Vh,Vl = 69632
#define ASMEM (2 * ABUF)          // 139264

__global__ __launch_bounds__(256)
void attn_mma(const __nv_bfloat16* __restrict__ Qh,
              const __nv_bfloat16* __restrict__ Ql,
              const __nv_bfloat16* __restrict__ Kh,
              const __nv_bfloat16* __restrict__ Kl,
              const __nv_bfloat16* __restrict__ Vh,
              const __nv_bfloat16* __restrict__ Vl,
              __nv_bfloat16* __restrict__ Oh,
              __nv_bfloat16* __restrict__ Ol)
{
    extern __shared__ char sm[];
    const uint32_t sb = smem_u32(sm);
    const int t = threadIdx.x, w = t >> 5, lane = t & 31;
    const int qt = gridDim.x - 1 - blockIdx.x;   // heavy tiles first
    const int bh = blockIdx.y;
    const int b = bh >> 4, h = bh & 15, hk = h >> 3;
    const int q0 = qt * 128;

    // ---- Load Q tile (hi at sb, lo at sb + 128*KROW) via cp.async ----
    {
        const char* gqh = (const char*)(Qh + ((size_t)(b * LL + q0)) * (HQ * DD) + h * DD);
        const char* gql = (const char*)(Ql + ((size_t)(b * LL + q0)) * (HQ * DD) + h * DD);
#pragma unroll
        for (int i = 0; i < 8; i++) {
            int idx = t + i * 256;
            int r = idx >> 4;
            int c = (idx & 15) << 4;
            cpa16(sb + r * KROW + c,               gqh + (size_t)r * 4096 + c);
            cpa16(sb + 128 * KROW + r * KROW + c,  gql + (size_t)r * 4096 + c);
        }
        CP_COMMIT();
        CP_WAIT(0);
        __syncthreads();
    }

    // ---- ldmatrix Q fragments into registers ----
    uint32_t qfh[8][4], qfl[8][4];
    {
        const int qq = lane >> 3, r8 = lane & 7;
        const uint32_t qaddr = sb + (w * 16 + (qq & 1) * 8 + r8) * KROW + (qq >> 1) * 16;
#pragma unroll
        for (int c = 0; c < 8; c++) {
            ldmx4(qaddr + c * 32, qfh[c]);
            ldmx4(qaddr + 128 * KROW + c * 32, qfl[c]);
        }
    }
    __syncthreads();

    float oacc[16][4];
#pragma unroll
    for (int v = 0; v < 16; v++)
#pragma unroll
        for (int e = 0; e < 4; e++) oacc[v][e] = 0.f;
    float m0 = -1e30f, m1 = -1e30f, l0 = 0.f, l1 = 0.f;

    const int NT = 2 * qt + 2;
    const size_t kvrow = (size_t)(HKV * DD) * 2;

    {
        const size_t roff = ((size_t)(b * LL)) * (HKV * DD) + hk * DD;
        const char* srcs[4] = {(const char*)(Kh + roff), (const char*)(Kl + roff),
                               (const char*)(Vh + roff), (const char*)(Vl + roff)};
#pragma unroll
        for (int i = 0; i < 16; i++) {
            int idx = t + i * 256;
            int mat = idx >> 10;
            int r = (idx >> 4) & 63;
            int c = (idx & 15) << 4;
            cpa16(sb + mat * ATILE + r * KROW + c, srcs[mat] + (size_t)r * kvrow + c);
        }
        CP_COMMIT();
    }

    const int g = lane >> 2;
    const int row0 = q0 + w * 16 + g;
    const int colq = (lane & 3) * 2;

    for (int kt = 0; kt < NT; kt++) {
        if (kt + 1 < NT) {
            const uint32_t nb = sb + ((kt + 1) & 1) * ABUF;
            const size_t roff = ((size_t)(b * LL + (kt + 1) * 64)) * (HKV * DD) + hk * DD;
            const char* srcs[4] = {(const char*)(Kh + roff), (const char*)(Kl + roff),
                                   (const char*)(Vh + roff), (const char*)(Vl + roff)};
#pragma unroll
            for (int i = 0; i < 16; i++) {
                int idx = t + i * 256;
                int mat = idx >> 10;
                int r = (idx >> 4) & 63;
                int c = (idx & 15) << 4;
                cpa16(nb + mat * ATILE + r * KROW + c, srcs[mat] + (size_t)r * kvrow + c);
            }
            CP_COMMIT();
            CP_WAIT(1);
        } else {
            CP_WAIT(0);
        }
        __syncthreads();

        const uint32_t kb = sb + (kt & 1) * ABUF;
        const int kv0 = kt * 64;

        // ---- S = Q K^T (bf16x3) ----
        float s_[8][4];
#pragma unroll
        for (int j = 0; j < 8; j++)
#pragma unroll
            for (int e = 0; e < 4; e++) s_[j][e] = 0.f;

        const uint32_t kaddr = kb + (lane & 7) * KROW + (lane >> 3) * 16;
#pragma unroll
        for (int c32 = 0; c32 < 4; c32++) {
#pragma unroll
            for (int j = 0; j < 8; j++) {
                uint32_t kfh[4], kfl[4];
                ldmx4(kaddr + j * 8 * KROW + c32 * 64, kfh);
                ldmx4(kaddr + ATILE + j * 8 * KROW + c32 * 64, kfl);
                uint32_t bh0[2] = {kfh[0], kfh[1]}, bh1[2] = {kfh[2], kfh[3]};
                uint32_t bl0[2] = {kfl[0], kfl[1]}, bl1[2] = {kfl[2], kfl[3]};
                mma16816(s_[j], qfh[2 * c32],     bh0);
                mma16816(s_[j], qfh[2 * c32 + 1], bh1);
                mma16816(s_[j], qfh[2 * c32],     bl0);
                mma16816(s_[j], qfh[2 * c32 + 1], bl1);
                mma16816(s_[j], qfl[2 * c32],     bh0);
                mma16816(s_[j], qfl[2 * c32 + 1], bh1);
            }
        }

        // ---- causal mask ----
#pragma unroll
        for (int j = 0; j < 8; j++) {
            int c0 = kv0 + 8 * j + colq;
            if (c0 > row0)     s_[j][0] = -1e30f;
            if (c0 + 1 > row0) s_[j][1] = -1e30f;
            if (c0 > row0 + 8)     s_[j][2] = -1e30f;
            if (c0 + 1 > row0 + 8) s_[j][3] = -1e30f;
        }

        // ---- online softmax ----
        float mx0 = -1e30f, mx1 = -1e30f;
#pragma unroll
        for (int j = 0; j < 8; j++) {
            mx0 = fmaxf(mx0, fmaxf(s_[j][0], s_[j][1]));
            mx1 = fmaxf(mx1, fmaxf(s_[j][2], s_[j][3]));
        }
        mx0 = fmaxf(mx0, __shfl_xor_sync(0xffffffffu, mx0, 1));
        mx0 = fmaxf(mx0, __shfl_xor_sync(0xffffffffu, mx0, 2));
        mx1 = fmaxf(mx1, __shfl_xor_sync(0xffffffffu, mx1, 1));
        mx1 = fmaxf(mx1, __shfl_xor_sync(0xffffffffu, mx1, 2));
        const float m0n = fmaxf(m0, mx0), m1n = fmaxf(m1, mx1);
        const float cr0 = __expf(m0 - m0n), cr1 = __expf(m1 - m1n);
        float sum0 = 0.f, sum1 = 0.f;
#pragma unroll
        for (int j = 0; j < 8; j++) {
            s_[j][0] = __expf(s_[j][0] - m0n); sum0 += s_[j][0];
            s_[j][1] = __expf(s_[j][1] - m0n); sum0 += s_[j][1];
            s_[j][2] = __expf(s_[j][2] - m1n); sum1 += s_[j][2];
            s_[j][3] = __expf(s_[j][3] - m1n); sum1 += s_[j][3];
        }
        sum0 += __shfl_xor_sync(0xffffffffu, sum0, 1);
        sum0 += __shfl_xor_sync(0xffffffffu, sum0, 2);
        sum1 += __shfl_xor_sync(0xffffffffu, sum1, 1);
        sum1 += __shfl_xor_sync(0xffffffffu, sum1, 2);
        l0 = l0 * cr0 + sum0;  m0 = m0n;
        l1 = l1 * cr1 + sum1;  m1 = m1n;
#pragma unroll
        for (int v = 0; v < 16; v++) {
            oacc[v][0] *= cr0; oacc[v][1] *= cr0;
            oacc[v][2] *= cr1; oacc[v][3] *= cr1;
        }

        // ---- pack P into A-fragments (hi/lo) ----
        uint32_t ph01[8], ph23[8], pl01[8], pl23[8];
#pragma unroll
        for (int j = 0; j < 8; j++) {
            __nv_bfloat162 h01 = __floats2bfloat162_rn(s_[j][0], s_[j][1]);
            __nv_bfloat162 h23 = __floats2bfloat162_rn(s_[j][2], s_[j][3]);
            ph01[j] = *(uint32_t*)&h01;
            ph23[j] = *(uint32_t*)&h23;
            __nv_bfloat162 lo01 = __floats2bfloat162_rn(
                s_[j][0] - __bfloat162float(h01.x),
                s_[j][1] - __bfloat162float(h01.y));
            __nv_bfloat162 lo23 = __floats2bfloat162_rn(
                s_[j][2] - __bfloat162float(h23.x),
                s_[j][3] - __bfloat162float(h23.y));
            pl01[j] = *(uint32_t*)&lo01;
            pl23[j] = *(uint32_t*)&lo23;
        }

        // ---- O += P V (bf16x3); V via ldmatrix.trans ----
        const uint32_t vaddr = kb + 2 * ATILE + lane * KROW;
#pragma unroll
        for (int t32 = 0; t32 < 2; t32++) {
            uint32_t Ah0[4] = {ph01[4*t32],   ph23[4*t32],   ph01[4*t32+1], ph23[4*t32+1]};
            uint32_t Ah1[4] = {ph01[4*t32+2], ph23[4*t32+2], ph01[4*t32+3], ph23[4*t32+3]};
            uint32_t Al0[4] = {pl01[4*t32],   pl23[4*t32],   pl01[4*t32+1], pl23[4*t32+1]};
            uint32_t Al1[4] = {pl01[4*t32+2], pl23[4*t32+2], pl01[4*t32+3], pl23[4*t32+3]};
#pragma unroll
            for (int v = 0; v < 16; v++) {
                uint32_t vfh[4], vfl[4];
                ldmx4t(vaddr + t32 * 32 * KROW + v * 16, vfh);
                ldmx4t(vaddr + ATILE + t32 * 32 * KROW + v * 16, vfl);
                uint32_t bh0[2] = {vfh[0], vfh[1]}, bh1[2] = {vfh[2], vfh[3]};
                uint32_t bl0[2] = {vfl[0], vfl[1]}, bl1[2] = {vfl[2], vfl[3]};
                mma16816(oacc[v], Ah0, bh0);
                mma16816(oacc[v], Ah1, bh1);
                mma16816(oacc[v], Ah0, bl0);
                mma16816(oacc[v], Ah1, bl1);
                mma16816(oacc[v], Al0, bh0);
                mma16816(oacc[v], Al1, bh1);
            }
        }
        __syncthreads();
    }

    // ---- epilogue: write split bf16 directly ----
    const float inv0 = 1.0f / l0, inv1 = 1.0f / l1;
    const size_t r0off = ((size_t)(b * LL + q0 + w * 16 + g)) * (HQ * DD) + h * DD + colq;
    const size_t r1off = r0off + 8 * (size_t)(HQ * DD);
#pragma unroll
    for (int v = 0; v < 16; v++) {
        float a0 = oacc[v][0] * inv0, a1 = oacc[v][1] * inv0;
        float a2 = oacc[v][2] * inv1, a3 = oacc[v][3] * inv1;
        __nv_bfloat162 h0 = __floats2bfloat162_rn(a0, a1);
        __nv_bfloat162 lo0 = __floats2bfloat162_rn(
            a0 - __bfloat162float(h0.x), a1 - __bfloat162float(h0.y));
        __nv_bfloat162 h1 = __floats2bfloat162_rn(a2, a3);
        __nv_bfloat162 lo1 = __floats2bfloat162_rn(
            a2 - __bfloat162float(h1.x), a3 - __bfloat162float(h1.y));
        *(__nv_bfloat162*)&Oh[r0off + 8 * v] = h0;
        *(__nv_bfloat162*)&Ol[r0off + 8 * v] = lo0;
        *(__nv_bfloat162*)&Oh[r1off + 8 * v] = h1;
        *(__nv_bfloat162*)&Ol[r1off + 8 * v] = lo1;
    }
}

// ---------------------------------------------------------------------------
// Launch
// ---------------------------------------------------------------------------
extern "C" void kernel_launch(void* const* d_in, const int* in_sizes, int n_in,
                              void* d_out, int out_size)
{
    const float* X  = (const float*)d_in[0];
    const float* Wq = (const float*)d_in[1];
    const float* bq = (const float*)d_in[2];
    const float* Wk = (const float*)d_in[3];
    const float* bk = (const float*)d_in[4];
    const float* Wv = (const float*)d_in[5];
    const float* bv = (const float*)d_in[6];
    const float* Wo = (const float*)d_in[7];
    float* out = (float*)d_out;

    float *qp, *kp;
    __nv_bfloat16 *ah, *al, *kh2, *kl2, *vh2, *vl2, *oh, *ol;
    __nv_bfloat16 *wqh, *wql, *wkh, *wkl, *wvh, *wvl, *woh, *wol;
    cudaGetSymbolAddress((void**)&qp, g_q);
    cudaGetSymbolAddress((void**)&kp, g_k);
    cudaGetSymbolAddress((void**)&ah, g_ah);
    cudaGetSymbolAddress((void**)&al, g_al);
    cudaGetSymbolAddress((void**)&kh2, g_kh2);
    cudaGetSymbolAddress((void**)&kl2, g_kl2);
    cudaGetSymbolAddress((void**)&vh2, g_vh2);
    cudaGetSymbolAddress((void**)&vl2, g_vl2);
    cudaGetSymbolAddress((void**)&oh, g_oh);
    cudaGetSymbolAddress((void**)&ol, g_ol);
    cudaGetSymbolAddress((void**)&wqh, g_wqh);
    cudaGetSymbolAddress((void**)&wql, g_wql);
    cudaGetSymbolAddress((void**)&wkh, g_wkh);
    cudaGetSymbolAddress((void**)&wkl, g_wkl);
    cudaGetSymbolAddress((void**)&wvh, g_wvh);
    cudaGetSymbolAddress((void**)&wvl, g_wvl);
    cudaGetSymbolAddress((void**)&woh, g_woh);
    cudaGetSymbolAddress((void**)&wol, g_wol);

    cudaFuncSetAttribute(gemm_qkv,
                         cudaFuncAttributeMaxDynamicSharedMemorySize, GSMEM_BYTES);
    cudaFuncSetAttribute(gemm_bf16x3,
                         cudaFuncAttributeMaxDynamicSharedMemorySize, GSMEM_BYTES);
    cudaFuncSetAttribute(attn_mma,
                         cudaFuncAttributeMaxDynamicSharedMemorySize, ASMEM);

    const int n4x = (int)((size_t)MROWS * EE / 4);
    const float scale = 0.08838834764831845f;   // 1/sqrt(128)

    // Split X + transpose/split all weights (one launch)
    split_kernel<<<(n4x + 255) / 256, 256>>>(X, ah, al, n4x);
    tsplit4_kernel<<<dim3(64, 64, 4), dim3(32, 8)>>>(
        Wq, wqh, wql, Wk, wkh, wkl, Wv, wvh, wvl, Wo, woh, wol);

    // Fused Q+K+V projections (Q,K fp32 pre-rope; V split bf16 final)
    gemm_qkv<<<640, 256, GSMEM_BYTES>>>(
        ah, al,
        wqh, wql, bq, qp,
        wkh, wkl, bk, kp,
        wvh, wvl, bv, vh2, vl2);

    // Fused RoPE + split for Q (scaled) and K
    rope_split2<<<dim3(MROWS, 2), 256>>>(qp, ah, al, kp, kh2, kl2, scale);

    // Attention on tensor cores -> split bf16 output
    attn_mma<<<dim3(LL / 128, BB * HQ), 256, ASMEM>>>(
        ah, al, kh2, kl2, vh2, vl2, oh, ol);

    // Output projection
    gemm_bf16x3<<<dim3(EE/128, MROWS/128), 256, GSMEM_BYTES>>>(
        oh, ol, woh, wol, out, MROWS, EE, EE);
}